// round 2
// baseline (speedup 1.0000x reference)
#include <cuda_runtime.h>

#define BATCH  4
#define TSEQ   2048
#define DMODEL 1024
#define NHEADS 16
#define DKH    64

#define ELEMS ((size_t)BATCH * TSEQ * DMODEL)

// Scratch buffers (static device globals — no runtime allocation).
__device__ float g_q[ELEMS];
__device__ float g_k[ELEMS];
__device__ float g_v[ELEMS];
__device__ float g_ctx[ELEMS];

// ---------------------------------------------------------------------------
// GEMM: C[M,N] = A[M,K] @ B[N,K]^T (+ bias). Both operands K-contiguous (NT).
// 128x128 block tile, BK=16, 256 threads, 8x8 register micro-tile.
// ---------------------------------------------------------------------------
__device__ __forceinline__ void gemm_body(const float* __restrict__ A,
                                          const float* __restrict__ B,
                                          const float* __restrict__ bias,
                                          float* __restrict__ C,
                                          int K, int N)
{
    __shared__ float As[16][132];  // [k][m], padded
    __shared__ float Bs[16][132];  // [k][n], padded

    const int tid = threadIdx.x;
    const int tx = tid & 15, ty = tid >> 4;
    const int bm = blockIdx.x * 128, bn = blockIdx.y * 128;
    const int lr  = tid >> 2;        // 0..63  (row within half-tile)
    const int lc4 = (tid & 3) * 4;   // 0,4,8,12 (k offset)

    float acc[8][8];
#pragma unroll
    for (int i = 0; i < 8; ++i)
#pragma unroll
        for (int j = 0; j < 8; ++j) acc[i][j] = 0.f;

    for (int k0 = 0; k0 < K; k0 += 16) {
#pragma unroll
        for (int hh = 0; hh < 2; ++hh) {
            const int r = lr + hh * 64;
            float4 a4 = *(const float4*)(A + (size_t)(bm + r) * K + k0 + lc4);
            float4 b4 = *(const float4*)(B + (size_t)(bn + r) * K + k0 + lc4);
            As[lc4 + 0][r] = a4.x; As[lc4 + 1][r] = a4.y;
            As[lc4 + 2][r] = a4.z; As[lc4 + 3][r] = a4.w;
            Bs[lc4 + 0][r] = b4.x; Bs[lc4 + 1][r] = b4.y;
            Bs[lc4 + 2][r] = b4.z; Bs[lc4 + 3][r] = b4.w;
        }
        __syncthreads();
#pragma unroll
        for (int kk = 0; kk < 16; ++kk) {
            float4 a0 = *(const float4*)&As[kk][ty * 8];
            float4 a1 = *(const float4*)&As[kk][ty * 8 + 4];
            float4 b0 = *(const float4*)&Bs[kk][tx * 8];
            float4 b1 = *(const float4*)&Bs[kk][tx * 8 + 4];
            float a[8] = {a0.x, a0.y, a0.z, a0.w, a1.x, a1.y, a1.z, a1.w};
            float b[8] = {b0.x, b0.y, b0.z, b0.w, b1.x, b1.y, b1.z, b1.w};
#pragma unroll
            for (int i = 0; i < 8; ++i)
#pragma unroll
                for (int j = 0; j < 8; ++j)
                    acc[i][j] = fmaf(a[i], b[j], acc[i][j]);
        }
        __syncthreads();
    }

#pragma unroll
    for (int i = 0; i < 8; ++i) {
        float* cp = C + (size_t)(bm + ty * 8 + i) * N + bn + tx * 8;
#pragma unroll
        for (int j = 0; j < 8; ++j) {
            float v = acc[i][j];
            if (bias) v += bias[bn + tx * 8 + j];
            cp[j] = v;
        }
    }
}

__global__ __launch_bounds__(256) void qkv_gemm(const float* __restrict__ x,
                                                const float* __restrict__ Wq,
                                                const float* __restrict__ Wk,
                                                const float* __restrict__ Wv)
{
    const float* B = (blockIdx.z == 0) ? Wq : (blockIdx.z == 1 ? Wk : Wv);
    float* C = (blockIdx.z == 0) ? g_q : (blockIdx.z == 1 ? g_k : g_v);
    gemm_body(x, B, nullptr, C, DMODEL, DMODEL);
}

__global__ __launch_bounds__(256) void out_gemm(const float* __restrict__ Wo,
                                                const float* __restrict__ bo,
                                                float* __restrict__ out)
{
    gemm_body(g_ctx, Wo, bo, out, DMODEL, DMODEL);
}

// ---------------------------------------------------------------------------
// Flash-style causal attention, fp32. One block per (q-tile of 64, head, batch).
// Q/K stored d-major in smem, P stored col-major, so all fragment reads are
// LDS.128 (FMA-bound, not LDS-bound). Online softmax, O accumulator in regs.
// ---------------------------------------------------------------------------
#define ASTR 68
#define ASMEM_FLOATS (4 * 64 * ASTR + 3 * 64)

__global__ __launch_bounds__(256) void attn_kernel()
{
    extern __shared__ float sm[];
    float* Qt   = sm;                 // [d][row]  64x68
    float* Kt   = Qt + 64 * ASTR;     // [d][col]  64x68
    float* Vs   = Kt + 64 * ASTR;     // [key][col] 64x68
    float* Pt   = Vs + 64 * ASTR;     // [col][row] 64x68 (scores/probs, transposed)
    float* mrow = Pt + 64 * ASTR;     // [64]
    float* lrow = mrow + 64;          // [64]
    float* rsc  = lrow + 64;          // [64]

    const int qt = blockIdx.x, h = blockIdx.y, b = blockIdx.z;
    const int tid = threadIdx.x;
    const int tx = tid & 15, ty = tid >> 4;
    const int r0 = ty * 4, c0 = tx * 4;

    const size_t base = ((size_t)b * TSEQ) * DMODEL + (size_t)h * DKH;
    const float* qb = g_q + base + (size_t)qt * 64 * DMODEL;
    const float* kb = g_k + base;
    const float* vb = g_v + base;
    float* ob = g_ctx + base + (size_t)qt * 64 * DMODEL;

    // Load Q tile, transposed to d-major, pre-scaled by 1/sqrt(dk)=0.125.
#pragma unroll
    for (int i = tid; i < 64 * 16; i += 256) {
        int r = i >> 4, c = (i & 15) * 4;
        float4 v = *(const float4*)(qb + (size_t)r * DMODEL + c);
        Qt[(c + 0) * ASTR + r] = v.x * 0.125f;
        Qt[(c + 1) * ASTR + r] = v.y * 0.125f;
        Qt[(c + 2) * ASTR + r] = v.z * 0.125f;
        Qt[(c + 3) * ASTR + r] = v.w * 0.125f;
    }
    if (tid < 64) { mrow[tid] = -1e30f; lrow[tid] = 0.f; }

    float o[4][4];
#pragma unroll
    for (int i = 0; i < 4; ++i)
#pragma unroll
        for (int j = 0; j < 4; ++j) o[i][j] = 0.f;

    __syncthreads();

    for (int kt = 0; kt <= qt; ++kt) {   // causal: skip tiles above diagonal
        const float* kbt = kb + (size_t)kt * 64 * DMODEL;
        const float* vbt = vb + (size_t)kt * 64 * DMODEL;
#pragma unroll
        for (int i = tid; i < 64 * 16; i += 256) {
            int r = i >> 4, c = (i & 15) * 4;
            float4 kv = *(const float4*)(kbt + (size_t)r * DMODEL + c);
            Kt[(c + 0) * ASTR + r] = kv.x;
            Kt[(c + 1) * ASTR + r] = kv.y;
            Kt[(c + 2) * ASTR + r] = kv.z;
            Kt[(c + 3) * ASTR + r] = kv.w;
            float4 vv = *(const float4*)(vbt + (size_t)r * DMODEL + c);
            float* vd = Vs + r * ASTR + c;
            vd[0] = vv.x; vd[1] = vv.y; vd[2] = vv.z; vd[3] = vv.w;
        }
        __syncthreads();

        // S = (Q*scale) K^T  — 4x4 micro-tile per thread, LDS.128 fragments.
        float s[4][4];
#pragma unroll
        for (int i = 0; i < 4; ++i)
#pragma unroll
            for (int j = 0; j < 4; ++j) s[i][j] = 0.f;

#pragma unroll 16
        for (int d = 0; d < 64; ++d) {
            float4 a  = *(const float4*)&Qt[d * ASTR + r0];
            float4 bb = *(const float4*)&Kt[d * ASTR + c0];
            float av[4] = {a.x, a.y, a.z, a.w};
            float bv[4] = {bb.x, bb.y, bb.z, bb.w};
#pragma unroll
            for (int i = 0; i < 4; ++i)
#pragma unroll
                for (int j = 0; j < 4; ++j)
                    s[i][j] = fmaf(av[i], bv[j], s[i][j]);
        }

        if (kt == qt) {  // diagonal tile: mask cols > rows
#pragma unroll
            for (int i = 0; i < 4; ++i)
#pragma unroll
                for (int j = 0; j < 4; ++j)
                    if (c0 + j > r0 + i) s[i][j] = -1e30f;
        }

        // Write scores transposed: Pt[col][row], vectorized over rows.
#pragma unroll
        for (int j = 0; j < 4; ++j)
            *(float4*)&Pt[(c0 + j) * ASTR + r0] =
                make_float4(s[0][j], s[1][j], s[2][j], s[3][j]);
        __syncthreads();

        // Online softmax update (thread r owns row r; column reads conflict-free).
        if (tid < 64) {
            const int r = tid;
            float mprev = mrow[r];
            float mx = mprev;
#pragma unroll 8
            for (int c = 0; c < 64; ++c) mx = fmaxf(mx, Pt[c * ASTR + r]);
            const float sc = __expf(mprev - mx);
            float sum = 0.f;
#pragma unroll 8
            for (int c = 0; c < 64; ++c) {
                float p = __expf(Pt[c * ASTR + r] - mx);
                Pt[c * ASTR + r] = p;
                sum += p;
            }
            lrow[r] = lrow[r] * sc + sum;
            mrow[r] = mx;
            rsc[r]  = sc;
        }
        __syncthreads();

        // Rescale running O and accumulate O += P @ V.
        float f[4];
#pragma unroll
        for (int i = 0; i < 4; ++i) f[i] = rsc[r0 + i];
#pragma unroll
        for (int i = 0; i < 4; ++i)
#pragma unroll
            for (int j = 0; j < 4; ++j) o[i][j] *= f[i];

#pragma unroll 16
        for (int kk = 0; kk < 64; ++kk) {
            float4 a  = *(const float4*)&Pt[kk * ASTR + r0];
            float4 bb = *(const float4*)&Vs[kk * ASTR + c0];
            float av[4] = {a.x, a.y, a.z, a.w};
            float bv[4] = {bb.x, bb.y, bb.z, bb.w};
#pragma unroll
            for (int i = 0; i < 4; ++i)
#pragma unroll
                for (int j = 0; j < 4; ++j)
                    o[i][j] = fmaf(av[i], bv[j], o[i][j]);
        }
        __syncthreads();  // protect Kt/Vs/Pt before next tile's loads
    }

    // Epilogue: divide by softmax denominator, write ctx (float4 stores).
    float inv[4];
#pragma unroll
    for (int i = 0; i < 4; ++i) inv[i] = 1.f / lrow[r0 + i];
#pragma unroll
    for (int i = 0; i < 4; ++i) {
        float4 out4 = make_float4(o[i][0] * inv[i], o[i][1] * inv[i],
                                  o[i][2] * inv[i], o[i][3] * inv[i]);
        *(float4*)(ob + (size_t)(r0 + i) * DMODEL + c0) = out4;
    }
}

// ---------------------------------------------------------------------------
extern "C" void kernel_launch(void* const* d_in, const int* in_sizes, int n_in,
                              void* d_out, int out_size)
{
    (void)in_sizes; (void)n_in; (void)out_size;
    const float* x  = (const float*)d_in[0];
    // d_in[1] is the causal mask — deterministic, handled analytically.
    const float* Wq = (const float*)d_in[2];
    const float* Wk = (const float*)d_in[3];
    const float* Wv = (const float*)d_in[4];
    const float* Wo = (const float*)d_in[5];
    const float* bo = (const float*)d_in[6];
    float* out = (float*)d_out;

    const int smem_bytes = ASMEM_FLOATS * (int)sizeof(float);  // 70400 B
    cudaFuncSetAttribute(attn_kernel,
                         cudaFuncAttributeMaxDynamicSharedMemorySize, smem_bytes);

    qkv_gemm<<<dim3(DMODEL * BATCH * TSEQ / (128 * DMODEL) * 0 + 64, 8, 3), 256>>>(x, Wq, Wk, Wv);
    attn_kernel<<<dim3(TSEQ / 64, NHEADS, BATCH), 256, smem_bytes>>>();
    out_gemm<<<dim3(64, 8, 1), 256>>>(Wo, bo, out);
}

// round 8
// speedup vs baseline: 1.4805x; 1.4805x over previous
#include <cuda_runtime.h>
#include <cuda_bf16.h>
#include <cstdint>

#define BATCH  4
#define TSEQ   2048
#define DMODEL 1024
#define NHEADS 16
#define DKH    64
#define MROWS  (BATCH * TSEQ)                 // 8192
#define ELEMS  ((size_t)MROWS * DMODEL)       // 8388608
#define WELEMS ((size_t)DMODEL * DMODEL)      // 1048576

// ---------------- device scratch (no runtime allocation) -------------------
__device__ float g_q[ELEMS];
__device__ float g_k[ELEMS];
__device__ float g_v[ELEMS];
__device__ float g_ctx[ELEMS];

__device__ __nv_bfloat16 g_xhi[ELEMS], g_xlo[ELEMS];
__device__ __nv_bfloat16 g_chi[ELEMS], g_clo[ELEMS];
__device__ __nv_bfloat16 g_wqhi[WELEMS], g_wqlo[WELEMS];
__device__ __nv_bfloat16 g_wkhi[WELEMS], g_wklo[WELEMS];
__device__ __nv_bfloat16 g_wvhi[WELEMS], g_wvlo[WELEMS];
__device__ __nv_bfloat16 g_wohi[WELEMS], g_wolo[WELEMS];

extern __shared__ __align__(1024) char dynsmem[];

__device__ __forceinline__ uint32_t s2u(const void* p) {
    uint32_t a;
    asm("{ .reg .u64 t; cvta.to.shared.u64 t, %1; cvt.u32.u64 %0, t; }"
        : "=r"(a) : "l"(p));
    return a;
}

// ---------------- fp32 -> bf16 hi/lo split ---------------------------------
__global__ __launch_bounds__(256) void cvt_split(const float* __restrict__ src,
                                                 __nv_bfloat16* __restrict__ hi,
                                                 __nv_bfloat16* __restrict__ lo,
                                                 int n8) {
    int i = blockIdx.x * blockDim.x + threadIdx.x;
    if (i >= n8) return;
    const float4* s4 = (const float4*)src;
    float4 a = s4[2 * i], b = s4[2 * i + 1];
    float v[8] = {a.x, a.y, a.z, a.w, b.x, b.y, b.z, b.w};
    uint4 hp, lp;
    unsigned short* hs = (unsigned short*)&hp;
    unsigned short* ls = (unsigned short*)&lp;
#pragma unroll
    for (int j = 0; j < 8; ++j) {
        __nv_bfloat16 h = __float2bfloat16_rn(v[j]);
        __nv_bfloat16 l = __float2bfloat16_rn(v[j] - __bfloat162float(h));
        hs[j] = *(unsigned short*)&h;
        ls[j] = *(unsigned short*)&l;
    }
    ((uint4*)hi)[i] = hp;
    ((uint4*)lo)[i] = lp;
}

// ---------------- mma.sync split-bf16 GEMM: C = A@B^T (+bias) --------------
// 128x128 tile, BK=32, 8 warps (2x4), warp tile 64x32.
// SMEM rows padded to 40 halves (80B) -> ldmatrix conflict-free.
#define BK     32
#define NCHUNK (DMODEL / BK)        // 32
#define STR    40                   // halves per smem row
#define OPT_BYTES (128 * STR * 2)   // 10240 per operand tile
#define STAGE_BYTES (4 * OPT_BYTES) // Ahi,Alo,Bhi,Blo = 40960
#define GEMM_SMEM (2 * STAGE_BYTES) // 81920

__device__ __forceinline__ void ldsm_x4(uint32_t* r, uint32_t addr) {
    asm volatile("ldmatrix.sync.aligned.m8n8.x4.shared.b16 {%0,%1,%2,%3}, [%4];"
                 : "=r"(r[0]), "=r"(r[1]), "=r"(r[2]), "=r"(r[3]) : "r"(addr));
}

__device__ __forceinline__ void mma16816(float* c, const uint32_t* a,
                                         const uint32_t* b) {
    asm volatile(
        "mma.sync.aligned.m16n8k16.row.col.f32.bf16.bf16.f32 "
        "{%0,%1,%2,%3}, {%4,%5,%6,%7}, {%8,%9}, {%0,%1,%2,%3};"
        : "+f"(c[0]), "+f"(c[1]), "+f"(c[2]), "+f"(c[3])
        : "r"(a[0]), "r"(a[1]), "r"(a[2]), "r"(a[3]), "r"(b[0]), "r"(b[1]));
}

__device__ __forceinline__ void load_chunk(uint32_t stb,
                                           const __nv_bfloat16* Ahi,
                                           const __nv_bfloat16* Alo,
                                           const __nv_bfloat16* Bhi,
                                           const __nv_bfloat16* Blo,
                                           int bm, int bn, int k0, int tid) {
    const __nv_bfloat16* srcs[4] = {Ahi, Alo, Bhi, Blo};
#pragma unroll
    for (int t = 0; t < 4; ++t) {
        const __nv_bfloat16* src = srcs[t];
        const int rowbase = (t < 2) ? bm : bn;
        const uint32_t tb = stb + t * OPT_BYTES;
#pragma unroll
        for (int j = 0; j < 2; ++j) {          // 512 16B units / 256 threads
            int u = tid + j * 256;
            int r = u >> 2, seg = u & 3;       // row 0..127, 16B seg 0..3
            uint32_t dst = tb + r * (STR * 2) + seg * 16;
            const void* g = src + (size_t)(rowbase + r) * DMODEL + k0 + seg * 8;
            asm volatile("cp.async.cg.shared.global [%0], [%1], 16;"
                         :: "r"(dst), "l"(g));
        }
    }
    asm volatile("cp.async.commit_group;" ::: "memory");
}

template <bool HASBIAS>
__device__ __forceinline__ void gemm_core(const __nv_bfloat16* __restrict__ Ahi,
                                          const __nv_bfloat16* __restrict__ Alo,
                                          const __nv_bfloat16* __restrict__ Bhi,
                                          const __nv_bfloat16* __restrict__ Blo,
                                          const float* __restrict__ bias,
                                          float* __restrict__ C) {
    const int tid = threadIdx.x;
    const int lane = tid & 31, warp = tid >> 5;
    const int wm = warp >> 2, wn = warp & 3;   // 2x4 warp grid
    const int bm = blockIdx.x * 128, bn = blockIdx.y * 128;
    const uint32_t sb = s2u(dynsmem);

    // ldmatrix lane offsets
    const int a_row = lane & 15;               // + m0
    const int a_colh = (lane >> 4) << 3;       // 0 or 8 (halves)
    const int b_row = (lane & 7) + ((lane & 16) >> 1);
    const int b_colh = lane & 8;               // 0 or 8

    float acc[4][4][4];
#pragma unroll
    for (int i = 0; i < 4; ++i)
#pragma unroll
        for (int j = 0; j < 4; ++j)
#pragma unroll
            for (int q = 0; q < 4; ++q) acc[i][j][q] = 0.f;

    load_chunk(sb, Ahi, Alo, Bhi, Blo, bm, bn, 0, tid);

    for (int k = 0; k < NCHUNK; ++k) {
        const uint32_t stb = sb + (uint32_t)(k & 1) * STAGE_BYTES;
        if (k + 1 < NCHUNK) {
            load_chunk(sb + (uint32_t)((k + 1) & 1) * STAGE_BYTES,
                       Ahi, Alo, Bhi, Blo, bm, bn, (k + 1) * BK, tid);
            asm volatile("cp.async.wait_group 1;" ::: "memory");
        } else {
            asm volatile("cp.async.wait_group 0;" ::: "memory");
        }
        __syncthreads();

#pragma unroll
        for (int ks = 0; ks < 2; ++ks) {       // two k16 steps per chunk
            const int kb = ks * 16;
            uint32_t ah[4][4], al[4][4], bh[4][2], bl[4][2];
#pragma unroll
            for (int mt = 0; mt < 4; ++mt) {
                uint32_t ra = stb + (uint32_t)(wm * 64 + mt * 16 + a_row) * (STR * 2)
                            + (uint32_t)(kb + a_colh) * 2;
                ldsm_x4(ah[mt], ra);
                ldsm_x4(al[mt], ra + OPT_BYTES);
            }
#pragma unroll
            for (int p = 0; p < 2; ++p) {      // each x4 covers two n-tiles
                uint32_t rb = stb + 2 * OPT_BYTES
                            + (uint32_t)(wn * 32 + p * 16 + b_row) * (STR * 2)
                            + (uint32_t)(kb + b_colh) * 2;
                uint32_t t[4];
                ldsm_x4(t, rb);
                bh[p * 2 + 0][0] = t[0]; bh[p * 2 + 0][1] = t[1];
                bh[p * 2 + 1][0] = t[2]; bh[p * 2 + 1][1] = t[3];
                ldsm_x4(t, rb + OPT_BYTES);
                bl[p * 2 + 0][0] = t[0]; bl[p * 2 + 0][1] = t[1];
                bl[p * 2 + 1][0] = t[2]; bl[p * 2 + 1][1] = t[3];
            }
#pragma unroll
            for (int mt = 0; mt < 4; ++mt)
#pragma unroll
                for (int nt = 0; nt < 4; ++nt) {
                    mma16816(acc[mt][nt], ah[mt], bh[nt]);
                    mma16816(acc[mt][nt], ah[mt], bl[nt]);
                    mma16816(acc[mt][nt], al[mt], bh[nt]);
                }
        }
        __syncthreads();
    }

    // Epilogue: c0,c1 -> (row, col..col+1); c2,c3 -> (row+8, ...)
    const int rbase = bm + wm * 64 + (lane >> 2);
    const int cbase = bn + wn * 32 + (lane & 3) * 2;
#pragma unroll
    for (int mt = 0; mt < 4; ++mt)
#pragma unroll
        for (int nt = 0; nt < 4; ++nt) {
            const int row = rbase + mt * 16;
            const int col = cbase + nt * 8;
            float2 v0 = make_float2(acc[mt][nt][0], acc[mt][nt][1]);
            float2 v1 = make_float2(acc[mt][nt][2], acc[mt][nt][3]);
            if (HASBIAS) {
                float2 bb = *(const float2*)(bias + col);
                v0.x += bb.x; v0.y += bb.y;
                v1.x += bb.x; v1.y += bb.y;
            }
            *(float2*)(C + (size_t)row * DMODEL + col) = v0;
            *(float2*)(C + (size_t)(row + 8) * DMODEL + col) = v1;
        }
}

__global__ __launch_bounds__(256) void qkv_gemm_tc() {
    const __nv_bfloat16 *bh, *bl;
    float* C;
    if (blockIdx.z == 0)      { bh = g_wqhi; bl = g_wqlo; C = g_q; }
    else if (blockIdx.z == 1) { bh = g_wkhi; bl = g_wklo; C = g_k; }
    else                      { bh = g_wvhi; bl = g_wvlo; C = g_v; }
    gemm_core<false>(g_xhi, g_xlo, bh, bl, nullptr, C);
}

__global__ __launch_bounds__(256) void out_gemm_tc(const float* __restrict__ bo,
                                                   float* __restrict__ out) {
    gemm_core<true>(g_chi, g_clo, g_wohi, g_wolo, bo, out);
}

// ---------------- fp32 flash attention (validated round-2 kernel) ----------
#define ASTR 68
#define ASMEM_FLOATS (4 * 64 * ASTR + 3 * 64)

__global__ __launch_bounds__(256) void attn_kernel() {
    float* sm = (float*)dynsmem;
    float* Qt   = sm;
    float* Kt   = Qt + 64 * ASTR;
    float* Vs   = Kt + 64 * ASTR;
    float* Pt   = Vs + 64 * ASTR;
    float* mrow = Pt + 64 * ASTR;
    float* lrow = mrow + 64;
    float* rsc  = lrow + 64;

    const int qt = blockIdx.x, h = blockIdx.y, b = blockIdx.z;
    const int tid = threadIdx.x;
    const int tx = tid & 15, ty = tid >> 4;
    const int r0 = ty * 4, c0 = tx * 4;

    const size_t base = ((size_t)b * TSEQ) * DMODEL + (size_t)h * DKH;
    const float* qb = g_q + base + (size_t)qt * 64 * DMODEL;
    const float* kb = g_k + base;
    const float* vb = g_v + base;
    float* ob = g_ctx + base + (size_t)qt * 64 * DMODEL;

#pragma unroll
    for (int i = tid; i < 64 * 16; i += 256) {
        int r = i >> 4, c = (i & 15) * 4;
        float4 v = *(const float4*)(qb + (size_t)r * DMODEL + c);
        Qt[(c + 0) * ASTR + r] = v.x * 0.125f;
        Qt[(c + 1) * ASTR + r] = v.y * 0.125f;
        Qt[(c + 2) * ASTR + r] = v.z * 0.125f;
        Qt[(c + 3) * ASTR + r] = v.w * 0.125f;
    }
    if (tid < 64) { mrow[tid] = -1e30f; lrow[tid] = 0.f; }

    float o[4][4];
#pragma unroll
    for (int i = 0; i < 4; ++i)
#pragma unroll
        for (int j = 0; j < 4; ++j) o[i][j] = 0.f;

    __syncthreads();

    for (int kt = 0; kt <= qt; ++kt) {
        const float* kbt = kb + (size_t)kt * 64 * DMODEL;
        const float* vbt = vb + (size_t)kt * 64 * DMODEL;
#pragma unroll
        for (int i = tid; i < 64 * 16; i += 256) {
            int r = i >> 4, c = (i & 15) * 4;
            float4 kv = *(const float4*)(kbt + (size_t)r * DMODEL + c);
            Kt[(c + 0) * ASTR + r] = kv.x;
            Kt[(c + 1) * ASTR + r] = kv.y;
            Kt[(c + 2) * ASTR + r] = kv.z;
            Kt[(c + 3) * ASTR + r] = kv.w;
            float4 vv = *(const float4*)(vbt + (size_t)r * DMODEL + c);
            float* vd = Vs + r * ASTR + c;
            vd[0] = vv.x; vd[1] = vv.y; vd[2] = vv.z; vd[3] = vv.w;
        }
        __syncthreads();

        float s[4][4];
#pragma unroll
        for (int i = 0; i < 4; ++i)
#pragma unroll
            for (int j = 0; j < 4; ++j) s[i][j] = 0.f;

#pragma unroll 16
        for (int d = 0; d < 64; ++d) {
            float4 a  = *(const float4*)&Qt[d * ASTR + r0];
            float4 bb = *(const float4*)&Kt[d * ASTR + c0];
            float av[4] = {a.x, a.y, a.z, a.w};
            float bv[4] = {bb.x, bb.y, bb.z, bb.w};
#pragma unroll
            for (int i = 0; i < 4; ++i)
#pragma unroll
                for (int j = 0; j < 4; ++j)
                    s[i][j] = fmaf(av[i], bv[j], s[i][j]);
        }

        if (kt == qt) {
#pragma unroll
            for (int i = 0; i < 4; ++i)
#pragma unroll
                for (int j = 0; j < 4; ++j)
                    if (c0 + j > r0 + i) s[i][j] = -1e30f;
        }

#pragma unroll
        for (int j = 0; j < 4; ++j)
            *(float4*)&Pt[(c0 + j) * ASTR + r0] =
                make_float4(s[0][j], s[1][j], s[2][j], s[3][j]);
        __syncthreads();

        if (tid < 64) {
            const int r = tid;
            float mprev = mrow[r];
            float mx = mprev;
#pragma unroll 8
            for (int c = 0; c < 64; ++c) mx = fmaxf(mx, Pt[c * ASTR + r]);
            const float sc = __expf(mprev - mx);
            float sum = 0.f;
#pragma unroll 8
            for (int c = 0; c < 64; ++c) {
                float p = __expf(Pt[c * ASTR + r] - mx);
                Pt[c * ASTR + r] = p;
                sum += p;
            }
            lrow[r] = lrow[r] * sc + sum;
            mrow[r] = mx;
            rsc[r]  = sc;
        }
        __syncthreads();

        float f[4];
#pragma unroll
        for (int i = 0; i < 4; ++i) f[i] = rsc[r0 + i];
#pragma unroll
        for (int i = 0; i < 4; ++i)
#pragma unroll
            for (int j = 0; j < 4; ++j) o[i][j] *= f[i];

#pragma unroll 16
        for (int kk = 0; kk < 64; ++kk) {
            float4 a  = *(const float4*)&Pt[kk * ASTR + r0];
            float4 bb = *(const float4*)&Vs[kk * ASTR + c0];
            float av[4] = {a.x, a.y, a.z, a.w};
            float bv[4] = {bb.x, bb.y, bb.z, bb.w};
#pragma unroll
            for (int i = 0; i < 4; ++i)
#pragma unroll
                for (int j = 0; j < 4; ++j)
                    o[i][j] = fmaf(av[i], bv[j], o[i][j]);
        }
        __syncthreads();
    }

    float inv[4];
#pragma unroll
    for (int i = 0; i < 4; ++i) inv[i] = 1.f / lrow[r0 + i];
#pragma unroll
    for (int i = 0; i < 4; ++i) {
        float4 out4 = make_float4(o[i][0] * inv[i], o[i][1] * inv[i],
                                  o[i][2] * inv[i], o[i][3] * inv[i]);
        *(float4*)(ob + (size_t)(r0 + i) * DMODEL + c0) = out4;
    }
}

// ---------------------------------------------------------------------------
extern "C" void kernel_launch(void* const* d_in, const int* in_sizes, int n_in,
                              void* d_out, int out_size) {
    (void)in_sizes; (void)n_in; (void)out_size;
    const float* x  = (const float*)d_in[0];
    // d_in[1]: causal mask — handled analytically.
    const float* Wq = (const float*)d_in[2];
    const float* Wk = (const float*)d_in[3];
    const float* Wv = (const float*)d_in[4];
    const float* Wo = (const float*)d_in[5];
    const float* bo = (const float*)d_in[6];
    float* out = (float*)d_out;

    __nv_bfloat16 *xhi, *xlo, *chi, *clo, *wh[4], *wl[4];
    float* ctxp;
    cudaGetSymbolAddress((void**)&xhi, g_xhi);
    cudaGetSymbolAddress((void**)&xlo, g_xlo);
    cudaGetSymbolAddress((void**)&chi, g_chi);
    cudaGetSymbolAddress((void**)&clo, g_clo);
    cudaGetSymbolAddress((void**)&wh[0], g_wqhi); cudaGetSymbolAddress((void**)&wl[0], g_wqlo);
    cudaGetSymbolAddress((void**)&wh[1], g_wkhi); cudaGetSymbolAddress((void**)&wl[1], g_wklo);
    cudaGetSymbolAddress((void**)&wh[2], g_wvhi); cudaGetSymbolAddress((void**)&wl[2], g_wvlo);
    cudaGetSymbolAddress((void**)&wh[3], g_wohi); cudaGetSymbolAddress((void**)&wl[3], g_wolo);
    cudaGetSymbolAddress((void**)&ctxp, g_ctx);

    const int attn_smem = ASMEM_FLOATS * (int)sizeof(float); // 70400
    cudaFuncSetAttribute(qkv_gemm_tc, cudaFuncAttributeMaxDynamicSharedMemorySize, GEMM_SMEM);
    cudaFuncSetAttribute(out_gemm_tc, cudaFuncAttributeMaxDynamicSharedMemorySize, GEMM_SMEM);
    cudaFuncSetAttribute(attn_kernel, cudaFuncAttributeMaxDynamicSharedMemorySize, attn_smem);

    cvt_split<<<(int)(ELEMS / 8 + 255) / 256, 256>>>(x, xhi, xlo, (int)(ELEMS / 8));
    const float* Ws[4] = {Wq, Wk, Wv, Wo};
    for (int i = 0; i < 4; ++i)
        cvt_split<<<(int)(WELEMS / 8 + 255) / 256, 256>>>(Ws[i], wh[i], wl[i], (int)(WELEMS / 8));

    qkv_gemm_tc<<<dim3(MROWS / 128, DMODEL / 128, 3), 256, GEMM_SMEM>>>();
    attn_kernel<<<dim3(TSEQ / 64, NHEADS, BATCH), 256, attn_smem>>>();
    cvt_split<<<(int)(ELEMS / 8 + 255) / 256, 256>>>(ctxp, chi, clo, (int)(ELEMS / 8));
    out_gemm_tc<<<dim3(MROWS / 128, DMODEL / 128, 1), 256, GEMM_SMEM>>>(bo, out);
}

// round 9
// speedup vs baseline: 2.9268x; 1.9769x over previous
#include <cuda_runtime.h>
#include <cuda_bf16.h>
#include <cstdint>

#define BATCH  4
#define TSEQ   2048
#define DMODEL 1024
#define NHEADS 16
#define DKH    64
#define MROWS  (BATCH * TSEQ)                 // 8192
#define ELEMS  ((size_t)MROWS * DMODEL)       // 8388608
#define WELEMS ((size_t)DMODEL * DMODEL)      // 1048576

// ---------------- device scratch (no runtime allocation) -------------------
__device__ __nv_bfloat16 g_qhi[ELEMS], g_qlo[ELEMS];
__device__ __nv_bfloat16 g_khi[ELEMS], g_klo[ELEMS];
__device__ __nv_bfloat16 g_vhi[ELEMS], g_vlo[ELEMS];
__device__ __nv_bfloat16 g_chi[ELEMS], g_clo[ELEMS];
__device__ __nv_bfloat16 g_xhi[ELEMS], g_xlo[ELEMS];
__device__ __nv_bfloat16 g_wqhi[WELEMS], g_wqlo[WELEMS];
__device__ __nv_bfloat16 g_wkhi[WELEMS], g_wklo[WELEMS];
__device__ __nv_bfloat16 g_wvhi[WELEMS], g_wvlo[WELEMS];
__device__ __nv_bfloat16 g_wohi[WELEMS], g_wolo[WELEMS];

extern __shared__ __align__(1024) char dynsmem[];

__device__ __forceinline__ uint32_t s2u(const void* p) {
    uint32_t a;
    asm("{ .reg .u64 t; cvta.to.shared.u64 t, %1; cvt.u32.u64 %0, t; }"
        : "=r"(a) : "l"(p));
    return a;
}

__device__ __forceinline__ void cp16(uint32_t dst, const void* src) {
    asm volatile("cp.async.cg.shared.global [%0], [%1], 16;"
                 :: "r"(dst), "l"(src));
}

__device__ __forceinline__ void ldsm_x4(uint32_t* r, uint32_t addr) {
    asm volatile("ldmatrix.sync.aligned.m8n8.x4.shared.b16 {%0,%1,%2,%3}, [%4];"
                 : "=r"(r[0]), "=r"(r[1]), "=r"(r[2]), "=r"(r[3]) : "r"(addr));
}

__device__ __forceinline__ void ldsm_x4_t(uint32_t* r, uint32_t addr) {
    asm volatile("ldmatrix.sync.aligned.m8n8.x4.trans.shared.b16 {%0,%1,%2,%3}, [%4];"
                 : "=r"(r[0]), "=r"(r[1]), "=r"(r[2]), "=r"(r[3]) : "r"(addr));
}

__device__ __forceinline__ void mma16816(float* c, const uint32_t* a,
                                         const uint32_t* b) {
    asm volatile(
        "mma.sync.aligned.m16n8k16.row.col.f32.bf16.bf16.f32 "
        "{%0,%1,%2,%3}, {%4,%5,%6,%7}, {%8,%9}, {%0,%1,%2,%3};"
        : "+f"(c[0]), "+f"(c[1]), "+f"(c[2]), "+f"(c[3])
        : "r"(a[0]), "r"(a[1]), "r"(a[2]), "r"(a[3]), "r"(b[0]), "r"(b[1]));
}

// fp32 pair -> bf16x2 hi + bf16x2 lo (low half = first element)
__device__ __forceinline__ void split2(float x, float y, uint32_t& hi, uint32_t& lo) {
    __nv_bfloat16 hx = __float2bfloat16_rn(x);
    __nv_bfloat16 hy = __float2bfloat16_rn(y);
    __nv_bfloat16 lx = __float2bfloat16_rn(x - __bfloat162float(hx));
    __nv_bfloat16 ly = __float2bfloat16_rn(y - __bfloat162float(hy));
    __nv_bfloat162 H = __halves2bfloat162(hx, hy);
    __nv_bfloat162 L = __halves2bfloat162(lx, ly);
    hi = *reinterpret_cast<uint32_t*>(&H);
    lo = *reinterpret_cast<uint32_t*>(&L);
}

// ---------------- fp32 -> bf16 hi/lo split (x + weights only) --------------
__global__ __launch_bounds__(256) void cvt_split(const float* __restrict__ src,
                                                 __nv_bfloat16* __restrict__ hi,
                                                 __nv_bfloat16* __restrict__ lo,
                                                 int n8) {
    int i = blockIdx.x * blockDim.x + threadIdx.x;
    if (i >= n8) return;
    const float4* s4 = (const float4*)src;
    float4 a = s4[2 * i], b = s4[2 * i + 1];
    float v[8] = {a.x, a.y, a.z, a.w, b.x, b.y, b.z, b.w};
    uint4 hp, lp;
    unsigned short* hs = (unsigned short*)&hp;
    unsigned short* ls = (unsigned short*)&lp;
#pragma unroll
    for (int j = 0; j < 8; ++j) {
        __nv_bfloat16 h = __float2bfloat16_rn(v[j]);
        __nv_bfloat16 l = __float2bfloat16_rn(v[j] - __bfloat162float(h));
        hs[j] = *(unsigned short*)&h;
        ls[j] = *(unsigned short*)&l;
    }
    ((uint4*)hi)[i] = hp;
    ((uint4*)lo)[i] = lp;
}

// ---------------- mma.sync split-bf16 GEMM: C = A@B^T ----------------------
#define BK     32
#define NCHUNK (DMODEL / BK)        // 32
#define STR    40                   // halves per smem row
#define OPT_BYTES (128 * STR * 2)   // 10240 per operand tile
#define STAGE_BYTES (4 * OPT_BYTES) // 40960
#define GEMM_SMEM (2 * STAGE_BYTES) // 81920

__device__ __forceinline__ void load_chunk(uint32_t stb,
                                           const __nv_bfloat16* Ahi,
                                           const __nv_bfloat16* Alo,
                                           const __nv_bfloat16* Bhi,
                                           const __nv_bfloat16* Blo,
                                           int bm, int bn, int k0, int tid) {
    const __nv_bfloat16* srcs[4] = {Ahi, Alo, Bhi, Blo};
#pragma unroll
    for (int t = 0; t < 4; ++t) {
        const __nv_bfloat16* src = srcs[t];
        const int rowbase = (t < 2) ? bm : bn;
        const uint32_t tb = stb + t * OPT_BYTES;
#pragma unroll
        for (int j = 0; j < 2; ++j) {
            int u = tid + j * 256;
            int r = u >> 2, seg = u & 3;
            uint32_t dst = tb + r * (STR * 2) + seg * 16;
            const void* g = src + (size_t)(rowbase + r) * DMODEL + k0 + seg * 8;
            cp16(dst, g);
        }
    }
    asm volatile("cp.async.commit_group;" ::: "memory");
}

template <bool SPLITOUT, bool HASBIAS>
__device__ __forceinline__ void gemm_core(const __nv_bfloat16* __restrict__ Ahi,
                                          const __nv_bfloat16* __restrict__ Alo,
                                          const __nv_bfloat16* __restrict__ Bhi,
                                          const __nv_bfloat16* __restrict__ Blo,
                                          const float* __restrict__ bias,
                                          float* __restrict__ C,
                                          __nv_bfloat16* __restrict__ Chi,
                                          __nv_bfloat16* __restrict__ Clo,
                                          float scale) {
    const int tid = threadIdx.x;
    const int lane = tid & 31, warp = tid >> 5;
    const int wm = warp >> 2, wn = warp & 3;
    const int bm = blockIdx.x * 128, bn = blockIdx.y * 128;
    const uint32_t sb = s2u(dynsmem);

    const int a_row = lane & 15;
    const int a_colh = (lane >> 4) << 3;
    const int b_row = (lane & 7) + ((lane & 16) >> 1);
    const int b_colh = lane & 8;

    float acc[4][4][4];
#pragma unroll
    for (int i = 0; i < 4; ++i)
#pragma unroll
        for (int j = 0; j < 4; ++j)
#pragma unroll
            for (int q = 0; q < 4; ++q) acc[i][j][q] = 0.f;

    load_chunk(sb, Ahi, Alo, Bhi, Blo, bm, bn, 0, tid);

    for (int k = 0; k < NCHUNK; ++k) {
        const uint32_t stb = sb + (uint32_t)(k & 1) * STAGE_BYTES;
        if (k + 1 < NCHUNK) {
            load_chunk(sb + (uint32_t)((k + 1) & 1) * STAGE_BYTES,
                       Ahi, Alo, Bhi, Blo, bm, bn, (k + 1) * BK, tid);
            asm volatile("cp.async.wait_group 1;" ::: "memory");
        } else {
            asm volatile("cp.async.wait_group 0;" ::: "memory");
        }
        __syncthreads();

#pragma unroll
        for (int ks = 0; ks < 2; ++ks) {
            const int kb = ks * 16;
            uint32_t ah[4][4], al[4][4], bh[4][2], bl[4][2];
#pragma unroll
            for (int mt = 0; mt < 4; ++mt) {
                uint32_t ra = stb + (uint32_t)(wm * 64 + mt * 16 + a_row) * (STR * 2)
                            + (uint32_t)(kb + a_colh) * 2;
                ldsm_x4(ah[mt], ra);
                ldsm_x4(al[mt], ra + OPT_BYTES);
            }
#pragma unroll
            for (int p = 0; p < 2; ++p) {
                uint32_t rb = stb + 2 * OPT_BYTES
                            + (uint32_t)(wn * 32 + p * 16 + b_row) * (STR * 2)
                            + (uint32_t)(kb + b_colh) * 2;
                uint32_t t[4];
                ldsm_x4(t, rb);
                bh[p * 2 + 0][0] = t[0]; bh[p * 2 + 0][1] = t[1];
                bh[p * 2 + 1][0] = t[2]; bh[p * 2 + 1][1] = t[3];
                ldsm_x4(t, rb + OPT_BYTES);
                bl[p * 2 + 0][0] = t[0]; bl[p * 2 + 0][1] = t[1];
                bl[p * 2 + 1][0] = t[2]; bl[p * 2 + 1][1] = t[3];
            }
#pragma unroll
            for (int mt = 0; mt < 4; ++mt)
#pragma unroll
                for (int nt = 0; nt < 4; ++nt) {
                    mma16816(acc[mt][nt], ah[mt], bh[nt]);
                    mma16816(acc[mt][nt], ah[mt], bl[nt]);
                    mma16816(acc[mt][nt], al[mt], bh[nt]);
                }
        }
        __syncthreads();
    }

    const int rbase = bm + wm * 64 + (lane >> 2);
    const int cbase = bn + wn * 32 + (lane & 3) * 2;
#pragma unroll
    for (int mt = 0; mt < 4; ++mt)
#pragma unroll
        for (int nt = 0; nt < 4; ++nt) {
            const int row = rbase + mt * 16;
            const int col = cbase + nt * 8;
            if (SPLITOUT) {
                uint32_t hh, ll;
                split2(acc[mt][nt][0] * scale, acc[mt][nt][1] * scale, hh, ll);
                *(uint32_t*)(Chi + (size_t)row * DMODEL + col) = hh;
                *(uint32_t*)(Clo + (size_t)row * DMODEL + col) = ll;
                split2(acc[mt][nt][2] * scale, acc[mt][nt][3] * scale, hh, ll);
                *(uint32_t*)(Chi + (size_t)(row + 8) * DMODEL + col) = hh;
                *(uint32_t*)(Clo + (size_t)(row + 8) * DMODEL + col) = ll;
            } else {
                float2 v0 = make_float2(acc[mt][nt][0], acc[mt][nt][1]);
                float2 v1 = make_float2(acc[mt][nt][2], acc[mt][nt][3]);
                if (HASBIAS) {
                    float2 bb = *(const float2*)(bias + col);
                    v0.x += bb.x; v0.y += bb.y;
                    v1.x += bb.x; v1.y += bb.y;
                }
                *(float2*)(C + (size_t)row * DMODEL + col) = v0;
                *(float2*)(C + (size_t)(row + 8) * DMODEL + col) = v1;
            }
        }
}

__global__ __launch_bounds__(256) void qkv_gemm_tc() {
    const __nv_bfloat16 *bh, *bl;
    __nv_bfloat16 *ohi, *olo;
    float scale;
    if (blockIdx.z == 0)      { bh = g_wqhi; bl = g_wqlo; ohi = g_qhi; olo = g_qlo; scale = 0.125f; }
    else if (blockIdx.z == 1) { bh = g_wkhi; bl = g_wklo; ohi = g_khi; olo = g_klo; scale = 1.f; }
    else                      { bh = g_wvhi; bl = g_wvlo; ohi = g_vhi; olo = g_vlo; scale = 1.f; }
    gemm_core<true, false>(g_xhi, g_xlo, bh, bl, nullptr, nullptr, ohi, olo, scale);
}

__global__ __launch_bounds__(256) void out_gemm_tc(const float* __restrict__ bo,
                                                   float* __restrict__ out) {
    gemm_core<false, true>(g_chi, g_clo, g_wohi, g_wolo, bo, out, nullptr, nullptr, 1.f);
}

// ---------------- split-bf16 mma flash attention ----------------------------
// 128 q/block (8 warps x 16 rows), 64-key tiles, 2-stage K/V cp.async pipeline.
// smem: Qhi[128x72h] Qlo | stage{KHI,KLO,VHI,VLO each 64x72h} x2. pitch 144B.
#define APITCH 144
#define SQLO_OFF 18432
#define KV_BASE  36864
#define KV_STAGE 36864
#define ATTN_SMEM 110592

__device__ __forceinline__ void load_kv(uint32_t sb, int st, int kt,
                                        size_t trow0, int hc, int tid) {
    const uint32_t base = sb + KV_BASE + (uint32_t)st * KV_STAGE;
    const __nv_bfloat16* srcs[4] = {g_khi, g_klo, g_vhi, g_vlo};
#pragma unroll
    for (int i = 0; i < 8; ++i) {
        int u = tid + i * 256;                 // 0..2047
        int arr = u >> 9, r = (u >> 3) & 63, seg = u & 7;
        const void* src = srcs[arr] + (trow0 + (size_t)kt * 64 + r) * DMODEL
                        + hc + seg * 8;
        cp16(base + arr * 9216 + r * APITCH + seg * 16, src);
    }
    asm volatile("cp.async.commit_group;" ::: "memory");
}

__global__ __launch_bounds__(256) void attn_mma() {
    const int qt = blockIdx.x, h = blockIdx.y, b = blockIdx.z;
    const int tid = threadIdx.x, lane = tid & 31, w = tid >> 5;
    const uint32_t sb = s2u(dynsmem);
    const int nkt = 2 * qt + 2;
    const size_t trow0 = (size_t)b * TSEQ;
    const int hc = h * DKH;

    // Q tile async load (rows qt*128..+127, head cols)
#pragma unroll
    for (int i = 0; i < 8; ++i) {
        int u = tid + i * 256;                 // 0..2047
        int arr = u >> 10, r = (u >> 3) & 127, seg = u & 7;
        const void* src = (arr ? g_qlo : g_qhi)
            + (trow0 + (size_t)qt * 128 + r) * DMODEL + hc + seg * 8;
        cp16(sb + (arr ? SQLO_OFF : 0) + r * APITCH + seg * 16, src);
    }
    asm volatile("cp.async.commit_group;" ::: "memory");
    load_kv(sb, 0, 0, trow0, hc, tid);

    float m0 = -1e30f, m1 = -1e30f, l0 = 0.f, l1 = 0.f;
    float o[8][4];
#pragma unroll
    for (int j = 0; j < 8; ++j)
#pragma unroll
        for (int q = 0; q < 4; ++q) o[j][q] = 0.f;

    const int a_row = lane & 15;
    const int a_ch2 = ((lane >> 4) << 3) * 2;
    const int b_row = (lane & 7) + ((lane & 16) >> 1);
    const int b_ch2 = (lane & 8) * 2;
    const int rg0 = qt * 128 + 16 * w + (lane >> 2);
    const int cg0 = 2 * (lane & 3);

    for (int kt = 0; kt < nkt; ++kt) {
        if (kt + 1 < nkt) {
            load_kv(sb, (kt + 1) & 1, kt + 1, trow0, hc, tid);
            asm volatile("cp.async.wait_group 1;" ::: "memory");
        } else {
            asm volatile("cp.async.wait_group 0;" ::: "memory");
        }
        __syncthreads();
        const uint32_t kvb = sb + KV_BASE + (uint32_t)(kt & 1) * KV_STAGE;

        // S = Qs @ K^T (3-pass hi/lo), 16x64 per warp
        float s[8][4];
#pragma unroll
        for (int j = 0; j < 8; ++j)
#pragma unroll
            for (int q = 0; q < 4; ++q) s[j][q] = 0.f;

#pragma unroll
        for (int t = 0; t < 4; ++t) {          // dk k-steps
            uint32_t ah[4], al[4];
            uint32_t ra = sb + (uint32_t)(16 * w + a_row) * APITCH + t * 32 + a_ch2;
            ldsm_x4(ah, ra);
            ldsm_x4(al, ra + SQLO_OFF);
#pragma unroll
            for (int p = 0; p < 4; ++p) {      // key ntile pairs
                uint32_t th[4], tl[4];
                uint32_t rb = kvb + (uint32_t)(p * 16 + b_row) * APITCH + t * 32 + b_ch2;
                ldsm_x4(th, rb);
                ldsm_x4(tl, rb + 9216);
                uint32_t bh0[2] = {th[0], th[1]}, bl0[2] = {tl[0], tl[1]};
                mma16816(s[2 * p], ah, bh0);
                mma16816(s[2 * p], ah, bl0);
                mma16816(s[2 * p], al, bh0);
                uint32_t bh1[2] = {th[2], th[3]}, bl1[2] = {tl[2], tl[3]};
                mma16816(s[2 * p + 1], ah, bh1);
                mma16816(s[2 * p + 1], ah, bl1);
                mma16816(s[2 * p + 1], al, bh1);
            }
        }

        if (kt >= nkt - 2) {                   // causal mask (last two tiles)
            const int cb = kt * 64 + cg0;
#pragma unroll
            for (int j = 0; j < 8; ++j) {
                int c0 = cb + 8 * j;
                if (c0     > rg0)     s[j][0] = -1e9f;
                if (c0 + 1 > rg0)     s[j][1] = -1e9f;
                if (c0     > rg0 + 8) s[j][2] = -1e9f;
                if (c0 + 1 > rg0 + 8) s[j][3] = -1e9f;
            }
        }

        // online softmax (rows rg0, rg0+8 per thread; 4 lanes share a row)
        float tm0 = -1e30f, tm1 = -1e30f;
#pragma unroll
        for (int j = 0; j < 8; ++j) {
            tm0 = fmaxf(tm0, fmaxf(s[j][0], s[j][1]));
            tm1 = fmaxf(tm1, fmaxf(s[j][2], s[j][3]));
        }
        tm0 = fmaxf(tm0, __shfl_xor_sync(0xffffffffu, tm0, 1));
        tm0 = fmaxf(tm0, __shfl_xor_sync(0xffffffffu, tm0, 2));
        tm1 = fmaxf(tm1, __shfl_xor_sync(0xffffffffu, tm1, 1));
        tm1 = fmaxf(tm1, __shfl_xor_sync(0xffffffffu, tm1, 2));
        const float mn0 = fmaxf(m0, tm0), mn1 = fmaxf(m1, tm1);
        const float sc0 = __expf(m0 - mn0), sc1 = __expf(m1 - mn1);
        float sum0 = 0.f, sum1 = 0.f;
#pragma unroll
        for (int j = 0; j < 8; ++j) {
            s[j][0] = __expf(s[j][0] - mn0);
            s[j][1] = __expf(s[j][1] - mn0);
            s[j][2] = __expf(s[j][2] - mn1);
            s[j][3] = __expf(s[j][3] - mn1);
            sum0 += s[j][0] + s[j][1];
            sum1 += s[j][2] + s[j][3];
        }
        sum0 += __shfl_xor_sync(0xffffffffu, sum0, 1);
        sum0 += __shfl_xor_sync(0xffffffffu, sum0, 2);
        sum1 += __shfl_xor_sync(0xffffffffu, sum1, 1);
        sum1 += __shfl_xor_sync(0xffffffffu, sum1, 2);
        l0 = l0 * sc0 + sum0;
        l1 = l1 * sc1 + sum1;
        m0 = mn0; m1 = mn1;
#pragma unroll
        for (int j = 0; j < 8; ++j) {
            o[j][0] *= sc0; o[j][1] *= sc0;
            o[j][2] *= sc1; o[j][3] *= sc1;
        }

        // O += P @ V  (P fragments direct from S regs; V via ldmatrix.trans)
#pragma unroll
        for (int t = 0; t < 4; ++t) {          // key k-steps
            uint32_t phi[4], plo[4];
            split2(s[2 * t][0],     s[2 * t][1],     phi[0], plo[0]);
            split2(s[2 * t][2],     s[2 * t][3],     phi[1], plo[1]);
            split2(s[2 * t + 1][0], s[2 * t + 1][1], phi[2], plo[2]);
            split2(s[2 * t + 1][2], s[2 * t + 1][3], phi[3], plo[3]);
#pragma unroll
            for (int np = 0; np < 4; ++np) {   // d ntile pairs
                uint32_t th[4], tl[4];
                uint32_t rv = kvb + 18432
                            + (uint32_t)(t * 16 + (lane & 15)) * APITCH
                            + (uint32_t)(np * 16 + ((lane >> 4) << 3)) * 2;
                ldsm_x4_t(th, rv);
                ldsm_x4_t(tl, rv + 9216);
                uint32_t bh0[2] = {th[0], th[1]}, bl0[2] = {tl[0], tl[1]};
                mma16816(o[2 * np], phi, bh0);
                mma16816(o[2 * np], phi, bl0);
                mma16816(o[2 * np], plo, bh0);
                uint32_t bh1[2] = {th[2], th[3]}, bl1[2] = {tl[2], tl[3]};
                mma16816(o[2 * np + 1], phi, bh1);
                mma16816(o[2 * np + 1], phi, bl1);
                mma16816(o[2 * np + 1], plo, bh1);
            }
        }
        __syncthreads();
    }

    // epilogue: ctx = O / l, written as bf16 hi/lo for the output GEMM
    const float i0 = 1.f / l0, i1 = 1.f / l1;
    const size_t r0t = trow0 + (size_t)qt * 128 + 16 * w + (lane >> 2);
#pragma unroll
    for (int j = 0; j < 8; ++j) {
        const int col = hc + 8 * j + cg0;
        uint32_t hh, ll;
        split2(o[j][0] * i0, o[j][1] * i0, hh, ll);
        *(uint32_t*)(g_chi + r0t * DMODEL + col) = hh;
        *(uint32_t*)(g_clo + r0t * DMODEL + col) = ll;
        split2(o[j][2] * i1, o[j][3] * i1, hh, ll);
        *(uint32_t*)(g_chi + (r0t + 8) * DMODEL + col) = hh;
        *(uint32_t*)(g_clo + (r0t + 8) * DMODEL + col) = ll;
    }
}

// ---------------------------------------------------------------------------
extern "C" void kernel_launch(void* const* d_in, const int* in_sizes, int n_in,
                              void* d_out, int out_size) {
    (void)in_sizes; (void)n_in; (void)out_size;
    const float* x  = (const float*)d_in[0];
    // d_in[1]: causal mask — handled analytically.
    const float* Wq = (const float*)d_in[2];
    const float* Wk = (const float*)d_in[3];
    const float* Wv = (const float*)d_in[4];
    const float* Wo = (const float*)d_in[5];
    const float* bo = (const float*)d_in[6];
    float* out = (float*)d_out;

    __nv_bfloat16 *xhi, *xlo, *wh[4], *wl[4];
    cudaGetSymbolAddress((void**)&xhi, g_xhi);
    cudaGetSymbolAddress((void**)&xlo, g_xlo);
    cudaGetSymbolAddress((void**)&wh[0], g_wqhi); cudaGetSymbolAddress((void**)&wl[0], g_wqlo);
    cudaGetSymbolAddress((void**)&wh[1], g_wkhi); cudaGetSymbolAddress((void**)&wl[1], g_wklo);
    cudaGetSymbolAddress((void**)&wh[2], g_wvhi); cudaGetSymbolAddress((void**)&wl[2], g_wvlo);
    cudaGetSymbolAddress((void**)&wh[3], g_wohi); cudaGetSymbolAddress((void**)&wl[3], g_wolo);

    cudaFuncSetAttribute(qkv_gemm_tc, cudaFuncAttributeMaxDynamicSharedMemorySize, GEMM_SMEM);
    cudaFuncSetAttribute(out_gemm_tc, cudaFuncAttributeMaxDynamicSharedMemorySize, GEMM_SMEM);
    cudaFuncSetAttribute(attn_mma,    cudaFuncAttributeMaxDynamicSharedMemorySize, ATTN_SMEM);

    cvt_split<<<(int)(ELEMS / 8 + 255) / 256, 256>>>(x, xhi, xlo, (int)(ELEMS / 8));
    const float* Ws[4] = {Wq, Wk, Wv, Wo};
    for (int i = 0; i < 4; ++i)
        cvt_split<<<(int)(WELEMS / 8 + 255) / 256, 256>>>(Ws[i], wh[i], wl[i], (int)(WELEMS / 8));

    qkv_gemm_tc<<<dim3(MROWS / 128, DMODEL / 128, 3), 256, GEMM_SMEM>>>();
    attn_mma<<<dim3(TSEQ / 128, NHEADS, BATCH), 256, ATTN_SMEM>>>();
    out_gemm_tc<<<dim3(MROWS / 128, DMODEL / 128, 1), 256, GEMM_SMEM>>>(bo, out);
}

// round 10
// speedup vs baseline: 2.9866x; 1.0204x over previous
#include <cuda_runtime.h>
#include <cuda_bf16.h>
#include <cstdint>

#define BATCH  4
#define TSEQ   2048
#define DMODEL 1024
#define NHEADS 16
#define DKH    64
#define MROWS  (BATCH * TSEQ)                 // 8192
#define ELEMS  ((size_t)MROWS * DMODEL)       // 8388608
#define WELEMS ((size_t)DMODEL * DMODEL)      // 1048576

// ---------------- device scratch (no runtime allocation) -------------------
__device__ __nv_bfloat16 g_qhi[ELEMS], g_qlo[ELEMS];
__device__ __nv_bfloat16 g_khi[ELEMS], g_klo[ELEMS];
__device__ __nv_bfloat16 g_vhi[ELEMS], g_vlo[ELEMS];
__device__ __nv_bfloat16 g_chi[ELEMS], g_clo[ELEMS];
__device__ __nv_bfloat16 g_xhi[ELEMS], g_xlo[ELEMS];
__device__ __nv_bfloat16 g_wqhi[WELEMS], g_wqlo[WELEMS];
__device__ __nv_bfloat16 g_wkhi[WELEMS], g_wklo[WELEMS];
__device__ __nv_bfloat16 g_wvhi[WELEMS], g_wvlo[WELEMS];
__device__ __nv_bfloat16 g_wohi[WELEMS], g_wolo[WELEMS];

extern __shared__ __align__(1024) char dynsmem[];

__device__ __forceinline__ uint32_t s2u(const void* p) {
    uint32_t a;
    asm("{ .reg .u64 t; cvta.to.shared.u64 t, %1; cvt.u32.u64 %0, t; }"
        : "=r"(a) : "l"(p));
    return a;
}

__device__ __forceinline__ void cp16(uint32_t dst, const void* src) {
    asm volatile("cp.async.cg.shared.global [%0], [%1], 16;"
                 :: "r"(dst), "l"(src));
}

__device__ __forceinline__ void ldsm_x4(uint32_t* r, uint32_t addr) {
    asm volatile("ldmatrix.sync.aligned.m8n8.x4.shared.b16 {%0,%1,%2,%3}, [%4];"
                 : "=r"(r[0]), "=r"(r[1]), "=r"(r[2]), "=r"(r[3]) : "r"(addr));
}

__device__ __forceinline__ void ldsm_x4_t(uint32_t* r, uint32_t addr) {
    asm volatile("ldmatrix.sync.aligned.m8n8.x4.trans.shared.b16 {%0,%1,%2,%3}, [%4];"
                 : "=r"(r[0]), "=r"(r[1]), "=r"(r[2]), "=r"(r[3]) : "r"(addr));
}

__device__ __forceinline__ void mma16816(float* c, const uint32_t* a,
                                         const uint32_t* b) {
    asm volatile(
        "mma.sync.aligned.m16n8k16.row.col.f32.bf16.bf16.f32 "
        "{%0,%1,%2,%3}, {%4,%5,%6,%7}, {%8,%9}, {%0,%1,%2,%3};"
        : "+f"(c[0]), "+f"(c[1]), "+f"(c[2]), "+f"(c[3])
        : "r"(a[0]), "r"(a[1]), "r"(a[2]), "r"(a[3]), "r"(b[0]), "r"(b[1]));
}

// fp32 pair -> bf16x2 hi + bf16x2 lo
__device__ __forceinline__ void split2(float x, float y, uint32_t& hi, uint32_t& lo) {
    __nv_bfloat16 hx = __float2bfloat16_rn(x);
    __nv_bfloat16 hy = __float2bfloat16_rn(y);
    __nv_bfloat16 lx = __float2bfloat16_rn(x - __bfloat162float(hx));
    __nv_bfloat16 ly = __float2bfloat16_rn(y - __bfloat162float(hy));
    __nv_bfloat162 H = __halves2bfloat162(hx, hy);
    __nv_bfloat162 L = __halves2bfloat162(lx, ly);
    hi = *reinterpret_cast<uint32_t*>(&H);
    lo = *reinterpret_cast<uint32_t*>(&L);
}

// ---------------- fused fp32 -> bf16 hi/lo split (x + all 4 weights) -------
#define NX8 (ELEMS / 8)    // 1048576 = 2^20
#define NW8 (WELEMS / 8)   // 131072  = 2^17

__global__ __launch_bounds__(256) void cvt_all(const float* __restrict__ x,
                                               const float* __restrict__ Wq,
                                               const float* __restrict__ Wk,
                                               const float* __restrict__ Wv,
                                               const float* __restrict__ Wo) {
    int i = blockIdx.x * blockDim.x + threadIdx.x;
    const float* src;
    __nv_bfloat16 *hi, *lo;
    int off;
    if (i < (int)NX8) {
        src = x; hi = g_xhi; lo = g_xlo; off = i;
    } else {
        int j = i - (int)NX8;
        int w = j >> 17;              // / NW8
        off = j & (int)(NW8 - 1);     // % NW8
        if (w == 0)      { src = Wq; hi = g_wqhi; lo = g_wqlo; }
        else if (w == 1) { src = Wk; hi = g_wkhi; lo = g_wklo; }
        else if (w == 2) { src = Wv; hi = g_wvhi; lo = g_wvlo; }
        else             { src = Wo; hi = g_wohi; lo = g_wolo; }
    }
    const float4* s4 = (const float4*)src;
    float4 a = s4[2 * off], b = s4[2 * off + 1];
    float v[8] = {a.x, a.y, a.z, a.w, b.x, b.y, b.z, b.w};
    uint4 hp, lp;
    unsigned short* hs = (unsigned short*)&hp;
    unsigned short* ls = (unsigned short*)&lp;
#pragma unroll
    for (int j = 0; j < 8; ++j) {
        __nv_bfloat16 h = __float2bfloat16_rn(v[j]);
        __nv_bfloat16 l = __float2bfloat16_rn(v[j] - __bfloat162float(h));
        hs[j] = *(unsigned short*)&h;
        ls[j] = *(unsigned short*)&l;
    }
    ((uint4*)hi)[off] = hp;
    ((uint4*)lo)[off] = lp;
}

// ---------------- mma.sync split-bf16 GEMM: C = A@B^T (validated R9) -------
#define BK     32
#define NCHUNK (DMODEL / BK)        // 32
#define STR    40
#define OPT_BYTES (128 * STR * 2)   // 10240
#define STAGE_BYTES (4 * OPT_BYTES) // 40960
#define GEMM_SMEM (2 * STAGE_BYTES) // 81920

__device__ __forceinline__ void load_chunk(uint32_t stb,
                                           const __nv_bfloat16* Ahi,
                                           const __nv_bfloat16* Alo,
                                           const __nv_bfloat16* Bhi,
                                           const __nv_bfloat16* Blo,
                                           int bm, int bn, int k0, int tid) {
    const __nv_bfloat16* srcs[4] = {Ahi, Alo, Bhi, Blo};
#pragma unroll
    for (int t = 0; t < 4; ++t) {
        const __nv_bfloat16* src = srcs[t];
        const int rowbase = (t < 2) ? bm : bn;
        const uint32_t tb = stb + t * OPT_BYTES;
#pragma unroll
        for (int j = 0; j < 2; ++j) {
            int u = tid + j * 256;
            int r = u >> 2, seg = u & 3;
            uint32_t dst = tb + r * (STR * 2) + seg * 16;
            const void* g = src + (size_t)(rowbase + r) * DMODEL + k0 + seg * 8;
            cp16(dst, g);
        }
    }
    asm volatile("cp.async.commit_group;" ::: "memory");
}

template <bool SPLITOUT, bool HASBIAS>
__device__ __forceinline__ void gemm_core(const __nv_bfloat16* __restrict__ Ahi,
                                          const __nv_bfloat16* __restrict__ Alo,
                                          const __nv_bfloat16* __restrict__ Bhi,
                                          const __nv_bfloat16* __restrict__ Blo,
                                          const float* __restrict__ bias,
                                          float* __restrict__ C,
                                          __nv_bfloat16* __restrict__ Chi,
                                          __nv_bfloat16* __restrict__ Clo,
                                          float scale) {
    const int tid = threadIdx.x;
    const int lane = tid & 31, warp = tid >> 5;
    const int wm = warp >> 2, wn = warp & 3;
    const int bm = blockIdx.x * 128, bn = blockIdx.y * 128;
    const uint32_t sb = s2u(dynsmem);

    const int a_row = lane & 15;
    const int a_colh = (lane >> 4) << 3;
    const int b_row = (lane & 7) + ((lane & 16) >> 1);
    const int b_colh = lane & 8;

    float acc[4][4][4];
#pragma unroll
    for (int i = 0; i < 4; ++i)
#pragma unroll
        for (int j = 0; j < 4; ++j)
#pragma unroll
            for (int q = 0; q < 4; ++q) acc[i][j][q] = 0.f;

    load_chunk(sb, Ahi, Alo, Bhi, Blo, bm, bn, 0, tid);

    for (int k = 0; k < NCHUNK; ++k) {
        const uint32_t stb = sb + (uint32_t)(k & 1) * STAGE_BYTES;
        if (k + 1 < NCHUNK) {
            load_chunk(sb + (uint32_t)((k + 1) & 1) * STAGE_BYTES,
                       Ahi, Alo, Bhi, Blo, bm, bn, (k + 1) * BK, tid);
            asm volatile("cp.async.wait_group 1;" ::: "memory");
        } else {
            asm volatile("cp.async.wait_group 0;" ::: "memory");
        }
        __syncthreads();

#pragma unroll
        for (int ks = 0; ks < 2; ++ks) {
            const int kb = ks * 16;
            uint32_t ah[4][4], al[4][4], bh[4][2], bl[4][2];
#pragma unroll
            for (int mt = 0; mt < 4; ++mt) {
                uint32_t ra = stb + (uint32_t)(wm * 64 + mt * 16 + a_row) * (STR * 2)
                            + (uint32_t)(kb + a_colh) * 2;
                ldsm_x4(ah[mt], ra);
                ldsm_x4(al[mt], ra + OPT_BYTES);
            }
#pragma unroll
            for (int p = 0; p < 2; ++p) {
                uint32_t rb = stb + 2 * OPT_BYTES
                            + (uint32_t)(wn * 32 + p * 16 + b_row) * (STR * 2)
                            + (uint32_t)(kb + b_colh) * 2;
                uint32_t t[4];
                ldsm_x4(t, rb);
                bh[p * 2 + 0][0] = t[0]; bh[p * 2 + 0][1] = t[1];
                bh[p * 2 + 1][0] = t[2]; bh[p * 2 + 1][1] = t[3];
                ldsm_x4(t, rb + OPT_BYTES);
                bl[p * 2 + 0][0] = t[0]; bl[p * 2 + 0][1] = t[1];
                bl[p * 2 + 1][0] = t[2]; bl[p * 2 + 1][1] = t[3];
            }
#pragma unroll
            for (int mt = 0; mt < 4; ++mt)
#pragma unroll
                for (int nt = 0; nt < 4; ++nt) {
                    mma16816(acc[mt][nt], ah[mt], bh[nt]);
                    mma16816(acc[mt][nt], ah[mt], bl[nt]);
                    mma16816(acc[mt][nt], al[mt], bh[nt]);
                }
        }
        __syncthreads();
    }

    const int rbase = bm + wm * 64 + (lane >> 2);
    const int cbase = bn + wn * 32 + (lane & 3) * 2;
#pragma unroll
    for (int mt = 0; mt < 4; ++mt)
#pragma unroll
        for (int nt = 0; nt < 4; ++nt) {
            const int row = rbase + mt * 16;
            const int col = cbase + nt * 8;
            if (SPLITOUT) {
                uint32_t hh, ll;
                split2(acc[mt][nt][0] * scale, acc[mt][nt][1] * scale, hh, ll);
                *(uint32_t*)(Chi + (size_t)row * DMODEL + col) = hh;
                *(uint32_t*)(Clo + (size_t)row * DMODEL + col) = ll;
                split2(acc[mt][nt][2] * scale, acc[mt][nt][3] * scale, hh, ll);
                *(uint32_t*)(Chi + (size_t)(row + 8) * DMODEL + col) = hh;
                *(uint32_t*)(Clo + (size_t)(row + 8) * DMODEL + col) = ll;
            } else {
                float2 v0 = make_float2(acc[mt][nt][0], acc[mt][nt][1]);
                float2 v1 = make_float2(acc[mt][nt][2], acc[mt][nt][3]);
                if (HASBIAS) {
                    float2 bb = *(const float2*)(bias + col);
                    v0.x += bb.x; v0.y += bb.y;
                    v1.x += bb.x; v1.y += bb.y;
                }
                *(float2*)(C + (size_t)row * DMODEL + col) = v0;
                *(float2*)(C + (size_t)(row + 8) * DMODEL + col) = v1;
            }
        }
}

__global__ __launch_bounds__(256) void qkv_gemm_tc() {
    const __nv_bfloat16 *bh, *bl;
    __nv_bfloat16 *ohi, *olo;
    float scale;
    if (blockIdx.z == 0)      { bh = g_wqhi; bl = g_wqlo; ohi = g_qhi; olo = g_qlo; scale = 0.125f; }
    else if (blockIdx.z == 1) { bh = g_wkhi; bl = g_wklo; ohi = g_khi; olo = g_klo; scale = 1.f; }
    else                      { bh = g_wvhi; bl = g_wvlo; ohi = g_vhi; olo = g_vlo; scale = 1.f; }
    gemm_core<true, false>(g_xhi, g_xlo, bh, bl, nullptr, nullptr, ohi, olo, scale);
}

__global__ __launch_bounds__(256) void out_gemm_tc(const float* __restrict__ bo,
                                                   float* __restrict__ out) {
    gemm_core<false, true>(g_chi, g_clo, g_wohi, g_wolo, bo, out, nullptr, nullptr, 1.f);
}

// ---------------- split-bf16 mma flash attention ----------------------------
// 128 q/block (8 warps x 16 rows), 64-key tiles.
// R10: Q fragments hoisted to registers; 3-stage KV cp.async pipeline,
// ONE __syncthreads per key tile (issue-after-compute ordering).
#define APITCH 144
#define SQLO_OFF 18432
#define KV_BASE  36864
#define KV_STAGE 36864
#define ATTN_SMEM (KV_BASE + 3 * KV_STAGE)   // 147456

__device__ __forceinline__ void load_kv(uint32_t sb, int st, int kt,
                                        size_t trow0, int hc, int tid) {
    const uint32_t base = sb + KV_BASE + (uint32_t)st * KV_STAGE;
    const __nv_bfloat16* srcs[4] = {g_khi, g_klo, g_vhi, g_vlo};
#pragma unroll
    for (int i = 0; i < 8; ++i) {
        int u = tid + i * 256;                 // 0..2047
        int arr = u >> 9, r = (u >> 3) & 63, seg = u & 7;
        const void* src = srcs[arr] + (trow0 + (size_t)kt * 64 + r) * DMODEL
                        + hc + seg * 8;
        cp16(base + arr * 9216 + r * APITCH + seg * 16, src);
    }
    asm volatile("cp.async.commit_group;" ::: "memory");
}

__global__ __launch_bounds__(256, 1) void attn_mma() {
    const int qt = blockIdx.x, h = blockIdx.y, b = blockIdx.z;
    const int tid = threadIdx.x, lane = tid & 31, w = tid >> 5;
    const uint32_t sb = s2u(dynsmem);
    const int nkt = 2 * qt + 2;
    const size_t trow0 = (size_t)b * TSEQ;
    const int hc = h * DKH;

    // Q tile async load (group 0)
#pragma unroll
    for (int i = 0; i < 8; ++i) {
        int u = tid + i * 256;
        int arr = u >> 10, r = (u >> 3) & 127, seg = u & 7;
        const void* src = (arr ? g_qlo : g_qhi)
            + (trow0 + (size_t)qt * 128 + r) * DMODEL + hc + seg * 8;
        cp16(sb + (arr ? SQLO_OFF : 0) + r * APITCH + seg * 16, src);
    }
    asm volatile("cp.async.commit_group;" ::: "memory");
    load_kv(sb, 0, 0, trow0, hc, tid);   // group 1
    load_kv(sb, 1, 1, trow0, hc, tid);   // group 2 (nkt >= 2 always)

    const int a_row = lane & 15;
    const int a_ch2 = ((lane >> 4) << 3) * 2;
    const int b_row = (lane & 7) + ((lane & 16) >> 1);
    const int b_ch2 = (lane & 8) * 2;
    const int rg0 = qt * 128 + 16 * w + (lane >> 2);
    const int cg0 = 2 * (lane & 3);

    // Wait Q (leave two KV groups in flight), hoist Q fragments to registers.
    asm volatile("cp.async.wait_group 2;" ::: "memory");
    __syncthreads();
    uint32_t qh[4][4], ql[4][4];
#pragma unroll
    for (int t = 0; t < 4; ++t) {
        uint32_t ra = sb + (uint32_t)(16 * w + a_row) * APITCH + t * 32 + a_ch2;
        ldsm_x4(qh[t], ra);
        ldsm_x4(ql[t], ra + SQLO_OFF);
    }

    float m0 = -1e30f, m1 = -1e30f, l0 = 0.f, l1 = 0.f;
    float o[8][4];
#pragma unroll
    for (int j = 0; j < 8; ++j)
#pragma unroll
        for (int q = 0; q < 4; ++q) o[j][q] = 0.f;

    for (int kt = 0; kt < nkt; ++kt) {
        // ensure stage kt%3 landed (own groups), then cross-thread via barrier
        if (kt == nkt - 1)
            asm volatile("cp.async.wait_group 0;" ::: "memory");
        else
            asm volatile("cp.async.wait_group 1;" ::: "memory");
        __syncthreads();
        const uint32_t kvb = sb + KV_BASE + (uint32_t)(kt % 3) * KV_STAGE;

        // S = Qs @ K^T (3-pass hi/lo), 16x64 per warp
        float s[8][4];
#pragma unroll
        for (int j = 0; j < 8; ++j)
#pragma unroll
            for (int q = 0; q < 4; ++q) s[j][q] = 0.f;

#pragma unroll
        for (int t = 0; t < 4; ++t) {
#pragma unroll
            for (int p = 0; p < 4; ++p) {
                uint32_t th[4], tl[4];
                uint32_t rb = kvb + (uint32_t)(p * 16 + b_row) * APITCH + t * 32 + b_ch2;
                ldsm_x4(th, rb);
                ldsm_x4(tl, rb + 9216);
                uint32_t bh0[2] = {th[0], th[1]}, bl0[2] = {tl[0], tl[1]};
                mma16816(s[2 * p], qh[t], bh0);
                mma16816(s[2 * p], qh[t], bl0);
                mma16816(s[2 * p], ql[t], bh0);
                uint32_t bh1[2] = {th[2], th[3]}, bl1[2] = {tl[2], tl[3]};
                mma16816(s[2 * p + 1], qh[t], bh1);
                mma16816(s[2 * p + 1], qh[t], bl1);
                mma16816(s[2 * p + 1], ql[t], bh1);
            }
        }

        if (kt >= nkt - 2) {                   // causal mask (last two tiles)
            const int cb = kt * 64 + cg0;
#pragma unroll
            for (int j = 0; j < 8; ++j) {
                int c0 = cb + 8 * j;
                if (c0     > rg0)     s[j][0] = -1e9f;
                if (c0 + 1 > rg0)     s[j][1] = -1e9f;
                if (c0     > rg0 + 8) s[j][2] = -1e9f;
                if (c0 + 1 > rg0 + 8) s[j][3] = -1e9f;
            }
        }

        // online softmax
        float tm0 = -1e30f, tm1 = -1e30f;
#pragma unroll
        for (int j = 0; j < 8; ++j) {
            tm0 = fmaxf(tm0, fmaxf(s[j][0], s[j][1]));
            tm1 = fmaxf(tm1, fmaxf(s[j][2], s[j][3]));
        }
        tm0 = fmaxf(tm0, __shfl_xor_sync(0xffffffffu, tm0, 1));
        tm0 = fmaxf(tm0, __shfl_xor_sync(0xffffffffu, tm0, 2));
        tm1 = fmaxf(tm1, __shfl_xor_sync(0xffffffffu, tm1, 1));
        tm1 = fmaxf(tm1, __shfl_xor_sync(0xffffffffu, tm1, 2));
        const float mn0 = fmaxf(m0, tm0), mn1 = fmaxf(m1, tm1);
        const float sc0 = __expf(m0 - mn0), sc1 = __expf(m1 - mn1);
        float sum0 = 0.f, sum1 = 0.f;
#pragma unroll
        for (int j = 0; j < 8; ++j) {
            s[j][0] = __expf(s[j][0] - mn0);
            s[j][1] = __expf(s[j][1] - mn0);
            s[j][2] = __expf(s[j][2] - mn1);
            s[j][3] = __expf(s[j][3] - mn1);
            sum0 += s[j][0] + s[j][1];
            sum1 += s[j][2] + s[j][3];
        }
        sum0 += __shfl_xor_sync(0xffffffffu, sum0, 1);
        sum0 += __shfl_xor_sync(0xffffffffu, sum0, 2);
        sum1 += __shfl_xor_sync(0xffffffffu, sum1, 1);
        sum1 += __shfl_xor_sync(0xffffffffu, sum1, 2);
        l0 = l0 * sc0 + sum0;
        l1 = l1 * sc1 + sum1;
        m0 = mn0; m1 = mn1;
#pragma unroll
        for (int j = 0; j < 8; ++j) {
            o[j][0] *= sc0; o[j][1] *= sc0;
            o[j][2] *= sc1; o[j][3] *= sc1;
        }

        // O += P @ V
#pragma unroll
        for (int t = 0; t < 4; ++t) {
            uint32_t phi[4], plo[4];
            split2(s[2 * t][0],     s[2 * t][1],     phi[0], plo[0]);
            split2(s[2 * t][2],     s[2 * t][3],     phi[1], plo[1]);
            split2(s[2 * t + 1][0], s[2 * t + 1][1], phi[2], plo[2]);
            split2(s[2 * t + 1][2], s[2 * t + 1][3], phi[3], plo[3]);
#pragma unroll
            for (int np = 0; np < 4; ++np) {
                uint32_t th[4], tl[4];
                uint32_t rv = kvb + 18432
                            + (uint32_t)(t * 16 + (lane & 15)) * APITCH
                            + (uint32_t)(np * 16 + ((lane >> 4) << 3)) * 2;
                ldsm_x4_t(th, rv);
                ldsm_x4_t(tl, rv + 9216);
                uint32_t bh0[2] = {th[0], th[1]}, bl0[2] = {tl[0], tl[1]};
                mma16816(o[2 * np], phi, bh0);
                mma16816(o[2 * np], phi, bl0);
                mma16816(o[2 * np], plo, bh0);
                uint32_t bh1[2] = {th[2], th[3]}, bl1[2] = {tl[2], tl[3]};
                mma16816(o[2 * np + 1], phi, bh1);
                mma16816(o[2 * np + 1], phi, bl1);
                mma16816(o[2 * np + 1], plo, bh1);
            }
        }

        // prefetch stage kt+2 (overwrites stage (kt-1)%3 — all warps passed
        // this iteration's barrier, so no reader of that stage remains)
        if (kt + 2 < nkt)
            load_kv(sb, (kt + 2) % 3, kt + 2, trow0, hc, tid);
    }

    // epilogue: ctx = O / l, written as bf16 hi/lo for the output GEMM
    const float i0 = 1.f / l0, i1 = 1.f / l1;
    const size_t r0t = trow0 + (size_t)qt * 128 + 16 * w + (lane >> 2);
#pragma unroll
    for (int j = 0; j < 8; ++j) {
        const int col = hc + 8 * j + cg0;
        uint32_t hh, ll;
        split2(o[j][0] * i0, o[j][1] * i0, hh, ll);
        *(uint32_t*)(g_chi + r0t * DMODEL + col) = hh;
        *(uint32_t*)(g_clo + r0t * DMODEL + col) = ll;
        split2(o[j][2] * i1, o[j][3] * i1, hh, ll);
        *(uint32_t*)(g_chi + (r0t + 8) * DMODEL + col) = hh;
        *(uint32_t*)(g_clo + (r0t + 8) * DMODEL + col) = ll;
    }
}

// ---------------------------------------------------------------------------
extern "C" void kernel_launch(void* const* d_in, const int* in_sizes, int n_in,
                              void* d_out, int out_size) {
    (void)in_sizes; (void)n_in; (void)out_size;
    const float* x  = (const float*)d_in[0];
    // d_in[1]: causal mask — handled analytically.
    const float* Wq = (const float*)d_in[2];
    const float* Wk = (const float*)d_in[3];
    const float* Wv = (const float*)d_in[4];
    const float* Wo = (const float*)d_in[5];
    const float* bo = (const float*)d_in[6];
    float* out = (float*)d_out;

    cudaFuncSetAttribute(qkv_gemm_tc, cudaFuncAttributeMaxDynamicSharedMemorySize, GEMM_SMEM);
    cudaFuncSetAttribute(out_gemm_tc, cudaFuncAttributeMaxDynamicSharedMemorySize, GEMM_SMEM);
    cudaFuncSetAttribute(attn_mma,    cudaFuncAttributeMaxDynamicSharedMemorySize, ATTN_SMEM);

    const int ntot8 = (int)(NX8 + 4 * NW8);            // 1572864
    cvt_all<<<ntot8 / 256, 256>>>(x, Wq, Wk, Wv, Wo);

    qkv_gemm_tc<<<dim3(MROWS / 128, DMODEL / 128, 3), 256, GEMM_SMEM>>>();
    attn_mma<<<dim3(TSEQ / 128, NHEADS, BATCH), 256, ATTN_SMEM>>>();
    out_gemm_tc<<<dim3(MROWS / 128, DMODEL / 128, 1), 256, GEMM_SMEM>>>(bo, out);
}

// round 11
// speedup vs baseline: 3.0121x; 1.0085x over previous
#include <cuda_runtime.h>
#include <cuda_bf16.h>
#include <cstdint>

#define BATCH  4
#define TSEQ   2048
#define DMODEL 1024
#define NHEADS 16
#define DKH    64
#define MROWS  (BATCH * TSEQ)                 // 8192
#define ELEMS  ((size_t)MROWS * DMODEL)       // 8388608
#define WELEMS ((size_t)DMODEL * DMODEL)      // 1048576

// ---------------- device scratch (no runtime allocation) -------------------
__device__ __nv_bfloat16 g_qhi[ELEMS], g_qlo[ELEMS];
__device__ __nv_bfloat16 g_khi[ELEMS], g_klo[ELEMS];
__device__ __nv_bfloat16 g_vhi[ELEMS], g_vlo[ELEMS];
__device__ __nv_bfloat16 g_chi[ELEMS], g_clo[ELEMS];
__device__ __nv_bfloat16 g_xhi[ELEMS], g_xlo[ELEMS];
__device__ __nv_bfloat16 g_wqhi[WELEMS], g_wqlo[WELEMS];
__device__ __nv_bfloat16 g_wkhi[WELEMS], g_wklo[WELEMS];
__device__ __nv_bfloat16 g_wvhi[WELEMS], g_wvlo[WELEMS];
__device__ __nv_bfloat16 g_wohi[WELEMS], g_wolo[WELEMS];

extern __shared__ __align__(1024) char dynsmem[];

__device__ __forceinline__ uint32_t s2u(const void* p) {
    uint32_t a;
    asm("{ .reg .u64 t; cvta.to.shared.u64 t, %1; cvt.u32.u64 %0, t; }"
        : "=r"(a) : "l"(p));
    return a;
}

__device__ __forceinline__ void cp16(uint32_t dst, const void* src) {
    asm volatile("cp.async.cg.shared.global [%0], [%1], 16;"
                 :: "r"(dst), "l"(src));
}

__device__ __forceinline__ void ldsm_x4(uint32_t* r, uint32_t addr) {
    asm volatile("ldmatrix.sync.aligned.m8n8.x4.shared.b16 {%0,%1,%2,%3}, [%4];"
                 : "=r"(r[0]), "=r"(r[1]), "=r"(r[2]), "=r"(r[3]) : "r"(addr));
}

__device__ __forceinline__ void ldsm_x4_t(uint32_t* r, uint32_t addr) {
    asm volatile("ldmatrix.sync.aligned.m8n8.x4.trans.shared.b16 {%0,%1,%2,%3}, [%4];"
                 : "=r"(r[0]), "=r"(r[1]), "=r"(r[2]), "=r"(r[3]) : "r"(addr));
}

__device__ __forceinline__ void mma16816(float* c, const uint32_t* a,
                                         const uint32_t* b) {
    asm volatile(
        "mma.sync.aligned.m16n8k16.row.col.f32.bf16.bf16.f32 "
        "{%0,%1,%2,%3}, {%4,%5,%6,%7}, {%8,%9}, {%0,%1,%2,%3};"
        : "+f"(c[0]), "+f"(c[1]), "+f"(c[2]), "+f"(c[3])
        : "r"(a[0]), "r"(a[1]), "r"(a[2]), "r"(a[3]), "r"(b[0]), "r"(b[1]));
}

// fp32 pair -> bf16x2 hi + bf16x2 lo
__device__ __forceinline__ void split2(float x, float y, uint32_t& hi, uint32_t& lo) {
    __nv_bfloat16 hx = __float2bfloat16_rn(x);
    __nv_bfloat16 hy = __float2bfloat16_rn(y);
    __nv_bfloat16 lx = __float2bfloat16_rn(x - __bfloat162float(hx));
    __nv_bfloat16 ly = __float2bfloat16_rn(y - __bfloat162float(hy));
    __nv_bfloat162 H = __halves2bfloat162(hx, hy);
    __nv_bfloat162 L = __halves2bfloat162(lx, ly);
    hi = *reinterpret_cast<uint32_t*>(&H);
    lo = *reinterpret_cast<uint32_t*>(&L);
}

// ---------------- fused fp32 -> bf16 hi/lo split (x + all 4 weights) -------
#define NX8 (ELEMS / 8)    // 2^20
#define NW8 (WELEMS / 8)   // 2^17

__global__ __launch_bounds__(256) void cvt_all(const float* __restrict__ x,
                                               const float* __restrict__ Wq,
                                               const float* __restrict__ Wk,
                                               const float* __restrict__ Wv,
                                               const float* __restrict__ Wo) {
    int i = blockIdx.x * blockDim.x + threadIdx.x;
    const float* src;
    __nv_bfloat16 *hi, *lo;
    int off;
    if (i < (int)NX8) {
        src = x; hi = g_xhi; lo = g_xlo; off = i;
    } else {
        int j = i - (int)NX8;
        int w = j >> 17;
        off = j & (int)(NW8 - 1);
        if (w == 0)      { src = Wq; hi = g_wqhi; lo = g_wqlo; }
        else if (w == 1) { src = Wk; hi = g_wkhi; lo = g_wklo; }
        else if (w == 2) { src = Wv; hi = g_wvhi; lo = g_wvlo; }
        else             { src = Wo; hi = g_wohi; lo = g_wolo; }
    }
    const float4* s4 = (const float4*)src;
    float4 a = s4[2 * off], b = s4[2 * off + 1];
    float v[8] = {a.x, a.y, a.z, a.w, b.x, b.y, b.z, b.w};
    uint4 hp, lp;
    unsigned short* hs = (unsigned short*)&hp;
    unsigned short* ls = (unsigned short*)&lp;
#pragma unroll
    for (int j = 0; j < 8; ++j) {
        __nv_bfloat16 h = __float2bfloat16_rn(v[j]);
        __nv_bfloat16 l = __float2bfloat16_rn(v[j] - __bfloat162float(h));
        hs[j] = *(unsigned short*)&h;
        ls[j] = *(unsigned short*)&l;
    }
    ((uint4*)hi)[off] = hp;
    ((uint4*)lo)[off] = lp;
}

// ---------------- mma.sync split-bf16 GEMM: C = A@B^T ----------------------
#define BK     32
#define NCHUNK (DMODEL / BK)        // 32
#define STR    40
#define OPT_BYTES (128 * STR * 2)   // 10240
#define STAGE_BYTES (4 * OPT_BYTES) // 40960
#define GEMM_SMEM (2 * STAGE_BYTES) // 81920

__device__ __forceinline__ void load_chunk(uint32_t stb,
                                           const __nv_bfloat16* Ahi,
                                           const __nv_bfloat16* Alo,
                                           const __nv_bfloat16* Bhi,
                                           const __nv_bfloat16* Blo,
                                           int bm, int bn, int k0, int tid) {
    const __nv_bfloat16* srcs[4] = {Ahi, Alo, Bhi, Blo};
#pragma unroll
    for (int t = 0; t < 4; ++t) {
        const __nv_bfloat16* src = srcs[t];
        const int rowbase = (t < 2) ? bm : bn;
        const uint32_t tb = stb + t * OPT_BYTES;
#pragma unroll
        for (int j = 0; j < 2; ++j) {
            int u = tid + j * 256;
            int r = u >> 2, seg = u & 3;
            uint32_t dst = tb + r * (STR * 2) + seg * 16;
            const void* g = src + (size_t)(rowbase + r) * DMODEL + k0 + seg * 8;
            cp16(dst, g);
        }
    }
    asm volatile("cp.async.commit_group;" ::: "memory");
}

template <bool SPLITOUT, bool HASBIAS>
__device__ __forceinline__ void gemm_core(const __nv_bfloat16* __restrict__ Ahi,
                                          const __nv_bfloat16* __restrict__ Alo,
                                          const __nv_bfloat16* __restrict__ Bhi,
                                          const __nv_bfloat16* __restrict__ Blo,
                                          const float* __restrict__ bias,
                                          float* __restrict__ C,
                                          __nv_bfloat16* __restrict__ Chi,
                                          __nv_bfloat16* __restrict__ Clo,
                                          float scale) {
    const int tid = threadIdx.x;
    const int lane = tid & 31, warp = tid >> 5;
    const int wm = warp >> 2, wn = warp & 3;
    const int bm = blockIdx.x * 128, bn = blockIdx.y * 128;
    const uint32_t sb = s2u(dynsmem);

    const int a_row = lane & 15;
    const int a_colh = (lane >> 4) << 3;
    const int b_row = (lane & 7) + ((lane & 16) >> 1);
    const int b_colh = lane & 8;

    float acc[4][4][4];
#pragma unroll
    for (int i = 0; i < 4; ++i)
#pragma unroll
        for (int j = 0; j < 4; ++j)
#pragma unroll
            for (int q = 0; q < 4; ++q) acc[i][j][q] = 0.f;

    load_chunk(sb, Ahi, Alo, Bhi, Blo, bm, bn, 0, tid);

    for (int k = 0; k < NCHUNK; ++k) {
        const uint32_t stb = sb + (uint32_t)(k & 1) * STAGE_BYTES;
        if (k + 1 < NCHUNK) {
            load_chunk(sb + (uint32_t)((k + 1) & 1) * STAGE_BYTES,
                       Ahi, Alo, Bhi, Blo, bm, bn, (k + 1) * BK, tid);
            asm volatile("cp.async.wait_group 1;" ::: "memory");
        } else {
            asm volatile("cp.async.wait_group 0;" ::: "memory");
        }
        __syncthreads();

#pragma unroll
        for (int ks = 0; ks < 2; ++ks) {
            const int kb = ks * 16;
            uint32_t ah[4][4], al[4][4], bh[4][2], bl[4][2];
#pragma unroll
            for (int mt = 0; mt < 4; ++mt) {
                uint32_t ra = stb + (uint32_t)(wm * 64 + mt * 16 + a_row) * (STR * 2)
                            + (uint32_t)(kb + a_colh) * 2;
                ldsm_x4(ah[mt], ra);
                ldsm_x4(al[mt], ra + OPT_BYTES);
            }
#pragma unroll
            for (int p = 0; p < 2; ++p) {
                uint32_t rb = stb + 2 * OPT_BYTES
                            + (uint32_t)(wn * 32 + p * 16 + b_row) * (STR * 2)
                            + (uint32_t)(kb + b_colh) * 2;
                uint32_t t[4];
                ldsm_x4(t, rb);
                bh[p * 2 + 0][0] = t[0]; bh[p * 2 + 0][1] = t[1];
                bh[p * 2 + 1][0] = t[2]; bh[p * 2 + 1][1] = t[3];
                ldsm_x4(t, rb + OPT_BYTES);
                bl[p * 2 + 0][0] = t[0]; bl[p * 2 + 0][1] = t[1];
                bl[p * 2 + 1][0] = t[2]; bl[p * 2 + 1][1] = t[3];
            }
            // pass-major issue: 16 independent MMAs per pass, no RAW chains
#pragma unroll
            for (int mt = 0; mt < 4; ++mt)
#pragma unroll
                for (int nt = 0; nt < 4; ++nt)
                    mma16816(acc[mt][nt], ah[mt], bh[nt]);
#pragma unroll
            for (int mt = 0; mt < 4; ++mt)
#pragma unroll
                for (int nt = 0; nt < 4; ++nt)
                    mma16816(acc[mt][nt], ah[mt], bl[nt]);
#pragma unroll
            for (int mt = 0; mt < 4; ++mt)
#pragma unroll
                for (int nt = 0; nt < 4; ++nt)
                    mma16816(acc[mt][nt], al[mt], bh[nt]);
        }
        __syncthreads();
    }

    const int rbase = bm + wm * 64 + (lane >> 2);
    const int cbase = bn + wn * 32 + (lane & 3) * 2;
#pragma unroll
    for (int mt = 0; mt < 4; ++mt)
#pragma unroll
        for (int nt = 0; nt < 4; ++nt) {
            const int row = rbase + mt * 16;
            const int col = cbase + nt * 8;
            if (SPLITOUT) {
                uint32_t hh, ll;
                split2(acc[mt][nt][0] * scale, acc[mt][nt][1] * scale, hh, ll);
                *(uint32_t*)(Chi + (size_t)row * DMODEL + col) = hh;
                *(uint32_t*)(Clo + (size_t)row * DMODEL + col) = ll;
                split2(acc[mt][nt][2] * scale, acc[mt][nt][3] * scale, hh, ll);
                *(uint32_t*)(Chi + (size_t)(row + 8) * DMODEL + col) = hh;
                *(uint32_t*)(Clo + (size_t)(row + 8) * DMODEL + col) = ll;
            } else {
                float2 v0 = make_float2(acc[mt][nt][0], acc[mt][nt][1]);
                float2 v1 = make_float2(acc[mt][nt][2], acc[mt][nt][3]);
                if (HASBIAS) {
                    float2 bb = *(const float2*)(bias + col);
                    v0.x += bb.x; v0.y += bb.y;
                    v1.x += bb.x; v1.y += bb.y;
                }
                *(float2*)(C + (size_t)row * DMODEL + col) = v0;
                *(float2*)(C + (size_t)(row + 8) * DMODEL + col) = v1;
            }
        }
}

__global__ __launch_bounds__(256) void qkv_gemm_tc() {
    const __nv_bfloat16 *bh, *bl;
    __nv_bfloat16 *ohi, *olo;
    float scale;
    if (blockIdx.z == 0)      { bh = g_wqhi; bl = g_wqlo; ohi = g_qhi; olo = g_qlo; scale = 0.125f; }
    else if (blockIdx.z == 1) { bh = g_wkhi; bl = g_wklo; ohi = g_khi; olo = g_klo; scale = 1.f; }
    else                      { bh = g_wvhi; bl = g_wvlo; ohi = g_vhi; olo = g_vlo; scale = 1.f; }
    gemm_core<true, false>(g_xhi, g_xlo, bh, bl, nullptr, nullptr, ohi, olo, scale);
}

__global__ __launch_bounds__(256) void out_gemm_tc(const float* __restrict__ bo,
                                                   float* __restrict__ out) {
    gemm_core<false, true>(g_chi, g_clo, g_wohi, g_wolo, bo, out, nullptr, nullptr, 1.f);
}

// ---------------- split-bf16 mma flash attention ----------------------------
#define APITCH 144
#define SQLO_OFF 18432
#define KV_BASE  36864
#define KV_STAGE 36864
#define ATTN_SMEM (KV_BASE + 3 * KV_STAGE)   // 147456

__device__ __forceinline__ void load_kv(uint32_t sb, int st, int kt,
                                        size_t trow0, int hc, int tid) {
    const uint32_t base = sb + KV_BASE + (uint32_t)st * KV_STAGE;
    const __nv_bfloat16* srcs[4] = {g_khi, g_klo, g_vhi, g_vlo};
#pragma unroll
    for (int i = 0; i < 8; ++i) {
        int u = tid + i * 256;
        int arr = u >> 9, r = (u >> 3) & 63, seg = u & 7;
        const void* src = srcs[arr] + (trow0 + (size_t)kt * 64 + r) * DMODEL
                        + hc + seg * 8;
        cp16(base + arr * 9216 + r * APITCH + seg * 16, src);
    }
    asm volatile("cp.async.commit_group;" ::: "memory");
}

__global__ __launch_bounds__(256, 1) void attn_mma() {
    const int qt = blockIdx.x, h = blockIdx.y, b = blockIdx.z;
    const int tid = threadIdx.x, lane = tid & 31, w = tid >> 5;
    const uint32_t sb = s2u(dynsmem);
    const int nkt = 2 * qt + 2;
    const size_t trow0 = (size_t)b * TSEQ;
    const int hc = h * DKH;

#pragma unroll
    for (int i = 0; i < 8; ++i) {
        int u = tid + i * 256;
        int arr = u >> 10, r = (u >> 3) & 127, seg = u & 7;
        const void* src = (arr ? g_qlo : g_qhi)
            + (trow0 + (size_t)qt * 128 + r) * DMODEL + hc + seg * 8;
        cp16(sb + (arr ? SQLO_OFF : 0) + r * APITCH + seg * 16, src);
    }
    asm volatile("cp.async.commit_group;" ::: "memory");
    load_kv(sb, 0, 0, trow0, hc, tid);
    load_kv(sb, 1, 1, trow0, hc, tid);

    const int a_row = lane & 15;
    const int a_ch2 = ((lane >> 4) << 3) * 2;
    const int b_row = (lane & 7) + ((lane & 16) >> 1);
    const int b_ch2 = (lane & 8) * 2;
    const int rg0 = qt * 128 + 16 * w + (lane >> 2);
    const int cg0 = 2 * (lane & 3);

    asm volatile("cp.async.wait_group 2;" ::: "memory");
    __syncthreads();
    uint32_t qh[4][4], ql[4][4];
#pragma unroll
    for (int t = 0; t < 4; ++t) {
        uint32_t ra = sb + (uint32_t)(16 * w + a_row) * APITCH + t * 32 + a_ch2;
        ldsm_x4(qh[t], ra);
        ldsm_x4(ql[t], ra + SQLO_OFF);
    }

    float m0 = -1e30f, m1 = -1e30f, l0 = 0.f, l1 = 0.f;
    float o[8][4];
#pragma unroll
    for (int j = 0; j < 8; ++j)
#pragma unroll
        for (int q = 0; q < 4; ++q) o[j][q] = 0.f;

    for (int kt = 0; kt < nkt; ++kt) {
        if (kt == nkt - 1)
            asm volatile("cp.async.wait_group 0;" ::: "memory");
        else
            asm volatile("cp.async.wait_group 1;" ::: "memory");
        __syncthreads();
        const uint32_t kvb = sb + KV_BASE + (uint32_t)(kt % 3) * KV_STAGE;

        // S = Qs @ K^T — pass-major (8 independent MMAs per pass)
        float s[8][4];
#pragma unroll
        for (int j = 0; j < 8; ++j)
#pragma unroll
            for (int q = 0; q < 4; ++q) s[j][q] = 0.f;

#pragma unroll
        for (int t = 0; t < 4; ++t) {
            uint32_t th[4][4], tl[4][4];
#pragma unroll
            for (int p = 0; p < 4; ++p) {
                uint32_t rb = kvb + (uint32_t)(p * 16 + b_row) * APITCH + t * 32 + b_ch2;
                ldsm_x4(th[p], rb);
                ldsm_x4(tl[p], rb + 9216);
            }
#pragma unroll
            for (int p = 0; p < 4; ++p) {
                mma16816(s[2 * p],     qh[t], &th[p][0]);
                mma16816(s[2 * p + 1], qh[t], &th[p][2]);
            }
#pragma unroll
            for (int p = 0; p < 4; ++p) {
                mma16816(s[2 * p],     qh[t], &tl[p][0]);
                mma16816(s[2 * p + 1], qh[t], &tl[p][2]);
            }
#pragma unroll
            for (int p = 0; p < 4; ++p) {
                mma16816(s[2 * p],     ql[t], &th[p][0]);
                mma16816(s[2 * p + 1], ql[t], &th[p][2]);
            }
        }

        if (kt >= nkt - 2) {
            const int cb = kt * 64 + cg0;
#pragma unroll
            for (int j = 0; j < 8; ++j) {
                int c0 = cb + 8 * j;
                if (c0     > rg0)     s[j][0] = -1e9f;
                if (c0 + 1 > rg0)     s[j][1] = -1e9f;
                if (c0     > rg0 + 8) s[j][2] = -1e9f;
                if (c0 + 1 > rg0 + 8) s[j][3] = -1e9f;
            }
        }

        // online softmax
        float tm0 = -1e30f, tm1 = -1e30f;
#pragma unroll
        for (int j = 0; j < 8; ++j) {
            tm0 = fmaxf(tm0, fmaxf(s[j][0], s[j][1]));
            tm1 = fmaxf(tm1, fmaxf(s[j][2], s[j][3]));
        }
        tm0 = fmaxf(tm0, __shfl_xor_sync(0xffffffffu, tm0, 1));
        tm0 = fmaxf(tm0, __shfl_xor_sync(0xffffffffu, tm0, 2));
        tm1 = fmaxf(tm1, __shfl_xor_sync(0xffffffffu, tm1, 1));
        tm1 = fmaxf(tm1, __shfl_xor_sync(0xffffffffu, tm1, 2));
        const float mn0 = fmaxf(m0, tm0), mn1 = fmaxf(m1, tm1);
        const float sc0 = __expf(m0 - mn0), sc1 = __expf(m1 - mn1);
        float sum0 = 0.f, sum1 = 0.f;
#pragma unroll
        for (int j = 0; j < 8; ++j) {
            s[j][0] = __expf(s[j][0] - mn0);
            s[j][1] = __expf(s[j][1] - mn0);
            s[j][2] = __expf(s[j][2] - mn1);
            s[j][3] = __expf(s[j][3] - mn1);
            sum0 += s[j][0] + s[j][1];
            sum1 += s[j][2] + s[j][3];
        }
        sum0 += __shfl_xor_sync(0xffffffffu, sum0, 1);
        sum0 += __shfl_xor_sync(0xffffffffu, sum0, 2);
        sum1 += __shfl_xor_sync(0xffffffffu, sum1, 1);
        sum1 += __shfl_xor_sync(0xffffffffu, sum1, 2);
        l0 = l0 * sc0 + sum0;
        l1 = l1 * sc1 + sum1;
        m0 = mn0; m1 = mn1;
#pragma unroll
        for (int j = 0; j < 8; ++j) {
            o[j][0] *= sc0; o[j][1] *= sc0;
            o[j][2] *= sc1; o[j][3] *= sc1;
        }

        // O += P @ V — pass-major per k-step
#pragma unroll
        for (int t = 0; t < 4; ++t) {
            uint32_t phi[4], plo[4];
            split2(s[2 * t][0],     s[2 * t][1],     phi[0], plo[0]);
            split2(s[2 * t][2],     s[2 * t][3],     phi[1], plo[1]);
            split2(s[2 * t + 1][0], s[2 * t + 1][1], phi[2], plo[2]);
            split2(s[2 * t + 1][2], s[2 * t + 1][3], phi[3], plo[3]);
            uint32_t vh[4][4], vl[4][4];
#pragma unroll
            for (int np = 0; np < 4; ++np) {
                uint32_t rv = kvb + 18432
                            + (uint32_t)(t * 16 + (lane & 15)) * APITCH
                            + (uint32_t)(np * 16 + ((lane >> 4) << 3)) * 2;
                ldsm_x4_t(vh[np], rv);
                ldsm_x4_t(vl[np], rv + 9216);
            }
#pragma unroll
            for (int np = 0; np < 4; ++np) {
                mma16816(o[2 * np],     phi, &vh[np][0]);
                mma16816(o[2 * np + 1], phi, &vh[np][2]);
            }
#pragma unroll
            for (int np = 0; np < 4; ++np) {
                mma16816(o[2 * np],     phi, &vl[np][0]);
                mma16816(o[2 * np + 1], phi, &vl[np][2]);
            }
#pragma unroll
            for (int np = 0; np < 4; ++np) {
                mma16816(o[2 * np],     plo, &vh[np][0]);
                mma16816(o[2 * np + 1], plo, &vh[np][2]);
            }
        }

        if (kt + 2 < nkt)
            load_kv(sb, (kt + 2) % 3, kt + 2, trow0, hc, tid);
    }

    // epilogue: ctx = O / l, as bf16 hi/lo
    const float i0 = 1.f / l0, i1 = 1.f / l1;
    const size_t r0t = trow0 + (size_t)qt * 128 + 16 * w + (lane >> 2);
#pragma unroll
    for (int j = 0; j < 8; ++j) {
        const int col = hc + 8 * j + cg0;
        uint32_t hh, ll;
        split2(o[j][0] * i0, o[j][1] * i0, hh, ll);
        *(uint32_t*)(g_chi + r0t * DMODEL + col) = hh;
        *(uint32_t*)(g_clo + r0t * DMODEL + col) = ll;
        split2(o[j][2] * i1, o[j][3] * i1, hh, ll);
        *(uint32_t*)(g_chi + (r0t + 8) * DMODEL + col) = hh;
        *(uint32_t*)(g_clo + (r0t + 8) * DMODEL + col) = ll;
    }
}

// ---------------------------------------------------------------------------
extern "C" void kernel_launch(void* const* d_in, const int* in_sizes, int n_in,
                              void* d_out, int out_size) {
    (void)in_sizes; (void)n_in; (void)out_size;
    const float* x  = (const float*)d_in[0];
    // d_in[1]: causal mask — handled analytically.
    const float* Wq = (const float*)d_in[2];
    const float* Wk = (const float*)d_in[3];
    const float* Wv = (const float*)d_in[4];
    const float* Wo = (const float*)d_in[5];
    const float* bo = (const float*)d_in[6];
    float* out = (float*)d_out;

    cudaFuncSetAttribute(qkv_gemm_tc, cudaFuncAttributeMaxDynamicSharedMemorySize, GEMM_SMEM);
    cudaFuncSetAttribute(out_gemm_tc, cudaFuncAttributeMaxDynamicSharedMemorySize, GEMM_SMEM);
    cudaFuncSetAttribute(attn_mma,    cudaFuncAttributeMaxDynamicSharedMemorySize, ATTN_SMEM);

    const int ntot8 = (int)(NX8 + 4 * NW8);
    cvt_all<<<ntot8 / 256, 256>>>(x, Wq, Wk, Wv, Wo);

    qkv_gemm_tc<<<dim3(MROWS / 128, DMODEL / 128, 3), 256, GEMM_SMEM>>>();
    attn_mma<<<dim3(TSEQ / 128, NHEADS, BATCH), 256, ATTN_SMEM>>>();
    out_gemm_tc<<<dim3(MROWS / 128, DMODEL / 128, 1), 256, GEMM_SMEM>>>(bo, out);
}

// round 14
// speedup vs baseline: 3.2893x; 1.0920x over previous
#include <cuda_runtime.h>
#include <cuda_bf16.h>
#include <cstdint>

#define BATCH  4
#define TSEQ   2048
#define DMODEL 1024
#define NHEADS 16
#define DKH    64
#define MROWS  (BATCH * TSEQ)                 // 8192
#define ELEMS  ((size_t)MROWS * DMODEL)       // 8388608
#define WELEMS ((size_t)DMODEL * DMODEL)      // 1048576

// ---------------- device scratch (no runtime allocation) -------------------
__device__ __nv_bfloat16 g_qhi[ELEMS], g_qlo[ELEMS];
__device__ __nv_bfloat16 g_khi[ELEMS], g_klo[ELEMS];
__device__ __nv_bfloat16 g_vhi[ELEMS], g_vlo[ELEMS];
__device__ __nv_bfloat16 g_chi[ELEMS], g_clo[ELEMS];
__device__ __nv_bfloat16 g_xhi[ELEMS], g_xlo[ELEMS];
__device__ __nv_bfloat16 g_wqhi[WELEMS], g_wqlo[WELEMS];
__device__ __nv_bfloat16 g_wkhi[WELEMS], g_wklo[WELEMS];
__device__ __nv_bfloat16 g_wvhi[WELEMS], g_wvlo[WELEMS];
__device__ __nv_bfloat16 g_wohi[WELEMS], g_wolo[WELEMS];

extern __shared__ __align__(1024) char dynsmem[];

__device__ __forceinline__ uint32_t s2u(const void* p) {
    uint32_t a;
    asm("{ .reg .u64 t; cvta.to.shared.u64 t, %1; cvt.u32.u64 %0, t; }"
        : "=r"(a) : "l"(p));
    return a;
}

__device__ __forceinline__ void cp16(uint32_t dst, const void* src) {
    asm volatile("cp.async.cg.shared.global [%0], [%1], 16;"
                 :: "r"(dst), "l"(src));
}

__device__ __forceinline__ void ldsm_x4(uint32_t* r, uint32_t addr) {
    asm volatile("ldmatrix.sync.aligned.m8n8.x4.shared.b16 {%0,%1,%2,%3}, [%4];"
                 : "=r"(r[0]), "=r"(r[1]), "=r"(r[2]), "=r"(r[3]) : "r"(addr));
}

__device__ __forceinline__ void ldsm_x4_t(uint32_t* r, uint32_t addr) {
    asm volatile("ldmatrix.sync.aligned.m8n8.x4.trans.shared.b16 {%0,%1,%2,%3}, [%4];"
                 : "=r"(r[0]), "=r"(r[1]), "=r"(r[2]), "=r"(r[3]) : "r"(addr));
}

__device__ __forceinline__ void mma16816(float* c, const uint32_t* a,
                                         const uint32_t* b) {
    asm volatile(
        "mma.sync.aligned.m16n8k16.row.col.f32.bf16.bf16.f32 "
        "{%0,%1,%2,%3}, {%4,%5,%6,%7}, {%8,%9}, {%0,%1,%2,%3};"
        : "+f"(c[0]), "+f"(c[1]), "+f"(c[2]), "+f"(c[3])
        : "r"(a[0]), "r"(a[1]), "r"(a[2]), "r"(a[3]), "r"(b[0]), "r"(b[1]));
}

// fp32 pair -> bf16x2 hi + bf16x2 lo
__device__ __forceinline__ void split2(float x, float y, uint32_t& hi, uint32_t& lo) {
    __nv_bfloat16 hx = __float2bfloat16_rn(x);
    __nv_bfloat16 hy = __float2bfloat16_rn(y);
    __nv_bfloat16 lx = __float2bfloat16_rn(x - __bfloat162float(hx));
    __nv_bfloat16 ly = __float2bfloat16_rn(y - __bfloat162float(hy));
    __nv_bfloat162 H = __halves2bfloat162(hx, hy);
    __nv_bfloat162 L = __halves2bfloat162(lx, ly);
    hi = *reinterpret_cast<uint32_t*>(&H);
    lo = *reinterpret_cast<uint32_t*>(&L);
}

// ---------------- fused fp32 -> bf16 hi/lo split (x + all 4 weights) -------
#define NX8 (ELEMS / 8)    // 2^20
#define NW8 (WELEMS / 8)   // 2^17

__global__ __launch_bounds__(256) void cvt_all(const float* __restrict__ x,
                                               const float* __restrict__ Wq,
                                               const float* __restrict__ Wk,
                                               const float* __restrict__ Wv,
                                               const float* __restrict__ Wo) {
    int i = blockIdx.x * blockDim.x + threadIdx.x;
    const float* src;
    __nv_bfloat16 *hi, *lo;
    int off;
    if (i < (int)NX8) {
        src = x; hi = g_xhi; lo = g_xlo; off = i;
    } else {
        int j = i - (int)NX8;
        int w = j >> 17;
        off = j & (int)(NW8 - 1);
        if (w == 0)      { src = Wq; hi = g_wqhi; lo = g_wqlo; }
        else if (w == 1) { src = Wk; hi = g_wkhi; lo = g_wklo; }
        else if (w == 2) { src = Wv; hi = g_wvhi; lo = g_wvlo; }
        else             { src = Wo; hi = g_wohi; lo = g_wolo; }
    }
    const float4* s4 = (const float4*)src;
    float4 a = s4[2 * off], b = s4[2 * off + 1];
    float v[8] = {a.x, a.y, a.z, a.w, b.x, b.y, b.z, b.w};
    uint4 hp, lp;
    unsigned short* hs = (unsigned short*)&hp;
    unsigned short* ls = (unsigned short*)&lp;
#pragma unroll
    for (int j = 0; j < 8; ++j) {
        __nv_bfloat16 h = __float2bfloat16_rn(v[j]);
        __nv_bfloat16 l = __float2bfloat16_rn(v[j] - __bfloat162float(h));
        hs[j] = *(unsigned short*)&h;
        ls[j] = *(unsigned short*)&l;
    }
    ((uint4*)hi)[off] = hp;
    ((uint4*)lo)[off] = lp;
}

// ---------------- mma.sync split-bf16 GEMM: C = A@B^T ----------------------
// R14: 64B pitch + XOR swizzle (16B-aligned, conflict-free), 3 stages,
// ONE barrier per chunk, 2-chunk prefetch, 2 CTAs/SM (2*98304 = 196608B).
#define BK     32
#define NCHUNK (DMODEL / BK)        // 32
#define OPT_BYTES (128 * 64)        // 8192 per operand tile (no padding)
#define STAGE_BYTES (4 * OPT_BYTES) // 32768
#define GEMM_SMEM (3 * STAGE_BYTES) // 98304

// swizzled byte offset of 16B segment (row, col16) in a 128x64B tile
__device__ __forceinline__ uint32_t swz(uint32_t row, uint32_t col16) {
    return row * 64 + ((col16 ^ ((row >> 1) & 3)) << 4);
}

__device__ __forceinline__ void load_chunk(uint32_t stb,
                                           const __nv_bfloat16* Ahi,
                                           const __nv_bfloat16* Alo,
                                           const __nv_bfloat16* Bhi,
                                           const __nv_bfloat16* Blo,
                                           int bm, int bn, int k0, int tid) {
    const __nv_bfloat16* srcs[4] = {Ahi, Alo, Bhi, Blo};
#pragma unroll
    for (int t = 0; t < 4; ++t) {
        const __nv_bfloat16* src = srcs[t];
        const int rowbase = (t < 2) ? bm : bn;
        const uint32_t tb = stb + t * OPT_BYTES;
#pragma unroll
        for (int j = 0; j < 2; ++j) {
            int u = tid + j * 256;
            int r = u >> 2, seg = u & 3;
            uint32_t dst = tb + swz((uint32_t)r, (uint32_t)seg);
            const void* g = src + (size_t)(rowbase + r) * DMODEL + k0 + seg * 8;
            cp16(dst, g);
        }
    }
    asm volatile("cp.async.commit_group;" ::: "memory");
}

template <bool SPLITOUT, bool HASBIAS>
__device__ __forceinline__ void gemm_core(const __nv_bfloat16* __restrict__ Ahi,
                                          const __nv_bfloat16* __restrict__ Alo,
                                          const __nv_bfloat16* __restrict__ Bhi,
                                          const __nv_bfloat16* __restrict__ Blo,
                                          const float* __restrict__ bias,
                                          float* __restrict__ C,
                                          __nv_bfloat16* __restrict__ Chi,
                                          __nv_bfloat16* __restrict__ Clo,
                                          float scale) {
    const int tid = threadIdx.x;
    const int lane = tid & 31, warp = tid >> 5;
    const int wm = warp >> 2, wn = warp & 3;
    const int bm = blockIdx.x * 128, bn = blockIdx.y * 128;
    const uint32_t sb = s2u(dynsmem);

    const uint32_t a_row = lane & 15;          // row within 16-row tile
    const uint32_t a_c16 = (uint32_t)(lane >> 4);        // 0/1: +16B (8 halves)
    const uint32_t b_row = (lane & 7) + ((lane & 16) >> 1);
    const uint32_t b_c16 = (uint32_t)((lane >> 3) & 1);  // 0/1

    float acc[4][4][4];
#pragma unroll
    for (int i = 0; i < 4; ++i)
#pragma unroll
        for (int j = 0; j < 4; ++j)
#pragma unroll
            for (int q = 0; q < 4; ++q) acc[i][j][q] = 0.f;

    load_chunk(sb,               Ahi, Alo, Bhi, Blo, bm, bn, 0,  tid);
    load_chunk(sb + STAGE_BYTES, Ahi, Alo, Bhi, Blo, bm, bn, BK, tid);

    for (int k = 0; k < NCHUNK; ++k) {
        const uint32_t stb = sb + (uint32_t)(k % 3) * STAGE_BYTES;
        if (k == NCHUNK - 1)
            asm volatile("cp.async.wait_group 0;" ::: "memory");
        else
            asm volatile("cp.async.wait_group 1;" ::: "memory");
        __syncthreads();   // chunk k visible AND compute k-1 done on all warps
        if (k + 2 < NCHUNK)
            load_chunk(sb + (uint32_t)((k + 2) % 3) * STAGE_BYTES,
                       Ahi, Alo, Bhi, Blo, bm, bn, (k + 2) * BK, tid);

#pragma unroll
        for (int ks = 0; ks < 2; ++ks) {
            uint32_t ah[4][4], al[4][4], bh[4][2], bl[4][2];
#pragma unroll
            for (int mt = 0; mt < 4; ++mt) {
                uint32_t row = (uint32_t)(wm * 64 + mt * 16) + a_row;
                uint32_t ra = stb + swz(row, (uint32_t)(ks * 2) + a_c16);
                ldsm_x4(ah[mt], ra);
                ldsm_x4(al[mt], ra + OPT_BYTES);
            }
#pragma unroll
            for (int p = 0; p < 2; ++p) {
                uint32_t row = (uint32_t)(wn * 32 + p * 16) + b_row;
                uint32_t rb = stb + 2 * OPT_BYTES
                            + swz(row, (uint32_t)(ks * 2) + b_c16);
                uint32_t t[4];
                ldsm_x4(t, rb);
                bh[p * 2 + 0][0] = t[0]; bh[p * 2 + 0][1] = t[1];
                bh[p * 2 + 1][0] = t[2]; bh[p * 2 + 1][1] = t[3];
                ldsm_x4(t, rb + OPT_BYTES);
                bl[p * 2 + 0][0] = t[0]; bl[p * 2 + 0][1] = t[1];
                bl[p * 2 + 1][0] = t[2]; bl[p * 2 + 1][1] = t[3];
            }
#pragma unroll
            for (int mt = 0; mt < 4; ++mt)
#pragma unroll
                for (int nt = 0; nt < 4; ++nt)
                    mma16816(acc[mt][nt], ah[mt], bh[nt]);
#pragma unroll
            for (int mt = 0; mt < 4; ++mt)
#pragma unroll
                for (int nt = 0; nt < 4; ++nt)
                    mma16816(acc[mt][nt], ah[mt], bl[nt]);
#pragma unroll
            for (int mt = 0; mt < 4; ++mt)
#pragma unroll
                for (int nt = 0; nt < 4; ++nt)
                    mma16816(acc[mt][nt], al[mt], bh[nt]);
        }
    }

    const int rbase = bm + wm * 64 + (lane >> 2);
    const int cbase = bn + wn * 32 + (lane & 3) * 2;
#pragma unroll
    for (int mt = 0; mt < 4; ++mt)
#pragma unroll
        for (int nt = 0; nt < 4; ++nt) {
            const int row = rbase + mt * 16;
            const int col = cbase + nt * 8;
            if (SPLITOUT) {
                uint32_t hh, ll;
                split2(acc[mt][nt][0] * scale, acc[mt][nt][1] * scale, hh, ll);
                *(uint32_t*)(Chi + (size_t)row * DMODEL + col) = hh;
                *(uint32_t*)(Clo + (size_t)row * DMODEL + col) = ll;
                split2(acc[mt][nt][2] * scale, acc[mt][nt][3] * scale, hh, ll);
                *(uint32_t*)(Chi + (size_t)(row + 8) * DMODEL + col) = hh;
                *(uint32_t*)(Clo + (size_t)(row + 8) * DMODEL + col) = ll;
            } else {
                float2 v0 = make_float2(acc[mt][nt][0], acc[mt][nt][1]);
                float2 v1 = make_float2(acc[mt][nt][2], acc[mt][nt][3]);
                if (HASBIAS) {
                    float2 bb = *(const float2*)(bias + col);
                    v0.x += bb.x; v0.y += bb.y;
                    v1.x += bb.x; v1.y += bb.y;
                }
                *(float2*)(C + (size_t)row * DMODEL + col) = v0;
                *(float2*)(C + (size_t)(row + 8) * DMODEL + col) = v1;
            }
        }
}

__global__ __launch_bounds__(256, 2) void qkv_gemm_tc() {
    const __nv_bfloat16 *bh, *bl;
    __nv_bfloat16 *ohi, *olo;
    float scale;
    if (blockIdx.z == 0)      { bh = g_wqhi; bl = g_wqlo; ohi = g_qhi; olo = g_qlo; scale = 0.125f; }
    else if (blockIdx.z == 1) { bh = g_wkhi; bl = g_wklo; ohi = g_khi; olo = g_klo; scale = 1.f; }
    else                      { bh = g_wvhi; bl = g_wvlo; ohi = g_vhi; olo = g_vlo; scale = 1.f; }
    gemm_core<true, false>(g_xhi, g_xlo, bh, bl, nullptr, nullptr, ohi, olo, scale);
}

__global__ __launch_bounds__(256, 2) void out_gemm_tc(const float* __restrict__ bo,
                                                      float* __restrict__ out) {
    gemm_core<false, true>(g_chi, g_clo, g_wohi, g_wolo, bo, out, nullptr, nullptr, 1.f);
}

// ---------------- split-bf16 mma flash attention (validated R11) ------------
#define APITCH 144
#define SQLO_OFF 18432
#define KV_BASE  36864
#define KV_STAGE 36864
#define ATTN_SMEM (KV_BASE + 3 * KV_STAGE)   // 147456

__device__ __forceinline__ void load_kv(uint32_t sb, int st, int kt,
                                        size_t trow0, int hc, int tid) {
    const uint32_t base = sb + KV_BASE + (uint32_t)st * KV_STAGE;
    const __nv_bfloat16* srcs[4] = {g_khi, g_klo, g_vhi, g_vlo};
#pragma unroll
    for (int i = 0; i < 8; ++i) {
        int u = tid + i * 256;
        int arr = u >> 9, r = (u >> 3) & 63, seg = u & 7;
        const void* src = srcs[arr] + (trow0 + (size_t)kt * 64 + r) * DMODEL
                        + hc + seg * 8;
        cp16(base + arr * 9216 + r * APITCH + seg * 16, src);
    }
    asm volatile("cp.async.commit_group;" ::: "memory");
}

__global__ __launch_bounds__(256, 1) void attn_mma() {
    // heavy tiles first: large qt has the most key tiles
    const int qt = (int)gridDim.x - 1 - (int)blockIdx.x;
    const int h = blockIdx.y, b = blockIdx.z;
    const int tid = threadIdx.x, lane = tid & 31, w = tid >> 5;
    const uint32_t sb = s2u(dynsmem);
    const int nkt = 2 * qt + 2;
    const size_t trow0 = (size_t)b * TSEQ;
    const int hc = h * DKH;

#pragma unroll
    for (int i = 0; i < 8; ++i) {
        int u = tid + i * 256;
        int arr = u >> 10, r = (u >> 3) & 127, seg = u & 7;
        const void* src = (arr ? g_qlo : g_qhi)
            + (trow0 + (size_t)qt * 128 + r) * DMODEL + hc + seg * 8;
        cp16(sb + (arr ? SQLO_OFF : 0) + r * APITCH + seg * 16, src);
    }
    asm volatile("cp.async.commit_group;" ::: "memory");
    load_kv(sb, 0, 0, trow0, hc, tid);
    load_kv(sb, 1, 1, trow0, hc, tid);

    const int a_row = lane & 15;
    const int a_ch2 = ((lane >> 4) << 3) * 2;
    const int b_row = (lane & 7) + ((lane & 16) >> 1);
    const int b_ch2 = (lane & 8) * 2;
    const int rg0 = qt * 128 + 16 * w + (lane >> 2);
    const int cg0 = 2 * (lane & 3);

    asm volatile("cp.async.wait_group 2;" ::: "memory");
    __syncthreads();
    uint32_t qh[4][4], ql[4][4];
#pragma unroll
    for (int t = 0; t < 4; ++t) {
        uint32_t ra = sb + (uint32_t)(16 * w + a_row) * APITCH + t * 32 + a_ch2;
        ldsm_x4(qh[t], ra);
        ldsm_x4(ql[t], ra + SQLO_OFF);
    }

    float m0 = -1e30f, m1 = -1e30f, l0 = 0.f, l1 = 0.f;
    float o[8][4];
#pragma unroll
    for (int j = 0; j < 8; ++j)
#pragma unroll
        for (int q = 0; q < 4; ++q) o[j][q] = 0.f;

    for (int kt = 0; kt < nkt; ++kt) {
        if (kt == nkt - 1)
            asm volatile("cp.async.wait_group 0;" ::: "memory");
        else
            asm volatile("cp.async.wait_group 1;" ::: "memory");
        __syncthreads();
        const uint32_t kvb = sb + KV_BASE + (uint32_t)(kt % 3) * KV_STAGE;

        float s[8][4];
#pragma unroll
        for (int j = 0; j < 8; ++j)
#pragma unroll
            for (int q = 0; q < 4; ++q) s[j][q] = 0.f;

#pragma unroll
        for (int t = 0; t < 4; ++t) {
            uint32_t th[4][4], tl[4][4];
#pragma unroll
            for (int p = 0; p < 4; ++p) {
                uint32_t rb = kvb + (uint32_t)(p * 16 + b_row) * APITCH + t * 32 + b_ch2;
                ldsm_x4(th[p], rb);
                ldsm_x4(tl[p], rb + 9216);
            }
#pragma unroll
            for (int p = 0; p < 4; ++p) {
                mma16816(s[2 * p],     qh[t], &th[p][0]);
                mma16816(s[2 * p + 1], qh[t], &th[p][2]);
            }
#pragma unroll
            for (int p = 0; p < 4; ++p) {
                mma16816(s[2 * p],     qh[t], &tl[p][0]);
                mma16816(s[2 * p + 1], qh[t], &tl[p][2]);
            }
#pragma unroll
            for (int p = 0; p < 4; ++p) {
                mma16816(s[2 * p],     ql[t], &th[p][0]);
                mma16816(s[2 * p + 1], ql[t], &th[p][2]);
            }
        }

        if (kt >= nkt - 2) {
            const int cb = kt * 64 + cg0;
#pragma unroll
            for (int j = 0; j < 8; ++j) {
                int c0 = cb + 8 * j;
                if (c0     > rg0)     s[j][0] = -1e9f;
                if (c0 + 1 > rg0)     s[j][1] = -1e9f;
                if (c0     > rg0 + 8) s[j][2] = -1e9f;
                if (c0 + 1 > rg0 + 8) s[j][3] = -1e9f;
            }
        }

        float tm0 = -1e30f, tm1 = -1e30f;
#pragma unroll
        for (int j = 0; j < 8; ++j) {
            tm0 = fmaxf(tm0, fmaxf(s[j][0], s[j][1]));
            tm1 = fmaxf(tm1, fmaxf(s[j][2], s[j][3]));
        }
        tm0 = fmaxf(tm0, __shfl_xor_sync(0xffffffffu, tm0, 1));
        tm0 = fmaxf(tm0, __shfl_xor_sync(0xffffffffu, tm0, 2));
        tm1 = fmaxf(tm1, __shfl_xor_sync(0xffffffffu, tm1, 1));
        tm1 = fmaxf(tm1, __shfl_xor_sync(0xffffffffu, tm1, 2));
        const float mn0 = fmaxf(m0, tm0), mn1 = fmaxf(m1, tm1);
        const float sc0 = __expf(m0 - mn0), sc1 = __expf(m1 - mn1);
        float sum0 = 0.f, sum1 = 0.f;
#pragma unroll
        for (int j = 0; j < 8; ++j) {
            s[j][0] = __expf(s[j][0] - mn0);
            s[j][1] = __expf(s[j][1] - mn0);
            s[j][2] = __expf(s[j][2] - mn1);
            s[j][3] = __expf(s[j][3] - mn1);
            sum0 += s[j][0] + s[j][1];
            sum1 += s[j][2] + s[j][3];
        }
        sum0 += __shfl_xor_sync(0xffffffffu, sum0, 1);
        sum0 += __shfl_xor_sync(0xffffffffu, sum0, 2);
        sum1 += __shfl_xor_sync(0xffffffffu, sum1, 1);
        sum1 += __shfl_xor_sync(0xffffffffu, sum1, 2);
        l0 = l0 * sc0 + sum0;
        l1 = l1 * sc1 + sum1;
        m0 = mn0; m1 = mn1;
#pragma unroll
        for (int j = 0; j < 8; ++j) {
            o[j][0] *= sc0; o[j][1] *= sc0;
            o[j][2] *= sc1; o[j][3] *= sc1;
        }

#pragma unroll
        for (int t = 0; t < 4; ++t) {
            uint32_t phi[4], plo[4];
            split2(s[2 * t][0],     s[2 * t][1],     phi[0], plo[0]);
            split2(s[2 * t][2],     s[2 * t][3],     phi[1], plo[1]);
            split2(s[2 * t + 1][0], s[2 * t + 1][1], phi[2], plo[2]);
            split2(s[2 * t + 1][2], s[2 * t + 1][3], phi[3], plo[3]);
            uint32_t vh[4][4], vl[4][4];
#pragma unroll
            for (int np = 0; np < 4; ++np) {
                uint32_t rv = kvb + 18432
                            + (uint32_t)(t * 16 + (lane & 15)) * APITCH
                            + (uint32_t)(np * 16 + ((lane >> 4) << 3)) * 2;
                ldsm_x4_t(vh[np], rv);
                ldsm_x4_t(vl[np], rv + 9216);
            }
#pragma unroll
            for (int np = 0; np < 4; ++np) {
                mma16816(o[2 * np],     phi, &vh[np][0]);
                mma16816(o[2 * np + 1], phi, &vh[np][2]);
            }
#pragma unroll
            for (int np = 0; np < 4; ++np) {
                mma16816(o[2 * np],     phi, &vl[np][0]);
                mma16816(o[2 * np + 1], phi, &vl[np][2]);
            }
#pragma unroll
            for (int np = 0; np < 4; ++np) {
                mma16816(o[2 * np],     plo, &vh[np][0]);
                mma16816(o[2 * np + 1], plo, &vh[np][2]);
            }
        }

        if (kt + 2 < nkt)
            load_kv(sb, (kt + 2) % 3, kt + 2, trow0, hc, tid);
    }

    const float i0 = 1.f / l0, i1 = 1.f / l1;
    const size_t r0t = trow0 + (size_t)qt * 128 + 16 * w + (lane >> 2);
#pragma unroll
    for (int j = 0; j < 8; ++j) {
        const int col = hc + 8 * j + cg0;
        uint32_t hh, ll;
        split2(o[j][0] * i0, o[j][1] * i0, hh, ll);
        *(uint32_t*)(g_chi + r0t * DMODEL + col) = hh;
        *(uint32_t*)(g_clo + r0t * DMODEL + col) = ll;
        split2(o[j][2] * i1, o[j][3] * i1, hh, ll);
        *(uint32_t*)(g_chi + (r0t + 8) * DMODEL + col) = hh;
        *(uint32_t*)(g_clo + (r0t + 8) * DMODEL + col) = ll;
    }
}

// ---------------------------------------------------------------------------
extern "C" void kernel_launch(void* const* d_in, const int* in_sizes, int n_in,
                              void* d_out, int out_size) {
    (void)in_sizes; (void)n_in; (void)out_size;
    const float* x  = (const float*)d_in[0];
    // d_in[1]: causal mask — handled analytically.
    const float* Wq = (const float*)d_in[2];
    const float* Wk = (const float*)d_in[3];
    const float* Wv = (const float*)d_in[4];
    const float* Wo = (const float*)d_in[5];
    const float* bo = (const float*)d_in[6];
    float* out = (float*)d_out;

    cudaFuncSetAttribute(qkv_gemm_tc, cudaFuncAttributeMaxDynamicSharedMemorySize, GEMM_SMEM);
    cudaFuncSetAttribute(out_gemm_tc, cudaFuncAttributeMaxDynamicSharedMemorySize, GEMM_SMEM);
    cudaFuncSetAttribute(attn_mma,    cudaFuncAttributeMaxDynamicSharedMemorySize, ATTN_SMEM);

    const int ntot8 = (int)(NX8 + 4 * NW8);
    cvt_all<<<ntot8 / 256, 256>>>(x, Wq, Wk, Wv, Wo);

    qkv_gemm_tc<<<dim3(MROWS / 128, DMODEL / 128, 3), 256, GEMM_SMEM>>>();
    attn_mma<<<dim3(TSEQ / 128, NHEADS, BATCH), 256, ATTN_SMEM>>>();
    out_gemm_tc<<<dim3(MROWS / 128, DMODEL / 128, 1), 256, GEMM_SMEM>>>(bo, out);
}

// round 16
// speedup vs baseline: 3.9954x; 1.2146x over previous
#include <cuda_runtime.h>
#include <cuda_bf16.h>
#include <cuda_fp16.h>
#include <cstdint>

#define BATCH  4
#define TSEQ   2048
#define DMODEL 1024
#define NHEADS 16
#define DKH    64
#define MROWS  (BATCH * TSEQ)                 // 8192
#define ELEMS  ((size_t)MROWS * DMODEL)       // 8388608
#define WELEMS ((size_t)DMODEL * DMODEL)      // 1048576

// ---------------- device scratch (no runtime allocation) -------------------
// attention operands: bf16 hi/lo (3-pass path, high accuracy for S)
__device__ __nv_bfloat16 g_qhi[ELEMS], g_qlo[ELEMS];
__device__ __nv_bfloat16 g_khi[ELEMS], g_klo[ELEMS];
__device__ __nv_bfloat16 g_vhi[ELEMS], g_vlo[ELEMS];
// projection-GEMM operands: fp16 (A split hi/lo, W single)
__device__ __half g_xh[ELEMS], g_xl[ELEMS];
__device__ __half g_ch[ELEMS], g_cl[ELEMS];
__device__ __half g_wq16[WELEMS], g_wk16[WELEMS], g_wv16[WELEMS], g_wo16[WELEMS];

extern __shared__ __align__(1024) char dynsmem[];

__device__ __forceinline__ uint32_t s2u(const void* p) {
    uint32_t a;
    asm("{ .reg .u64 t; cvta.to.shared.u64 t, %1; cvt.u32.u64 %0, t; }"
        : "=r"(a) : "l"(p));
    return a;
}

__device__ __forceinline__ void cp16(uint32_t dst, const void* src) {
    asm volatile("cp.async.cg.shared.global [%0], [%1], 16;"
                 :: "r"(dst), "l"(src));
}

__device__ __forceinline__ void ldsm_x4(uint32_t* r, uint32_t addr) {
    asm volatile("ldmatrix.sync.aligned.m8n8.x4.shared.b16 {%0,%1,%2,%3}, [%4];"
                 : "=r"(r[0]), "=r"(r[1]), "=r"(r[2]), "=r"(r[3]) : "r"(addr));
}

__device__ __forceinline__ void ldsm_x4_t(uint32_t* r, uint32_t addr) {
    asm volatile("ldmatrix.sync.aligned.m8n8.x4.trans.shared.b16 {%0,%1,%2,%3}, [%4];"
                 : "=r"(r[0]), "=r"(r[1]), "=r"(r[2]), "=r"(r[3]) : "r"(addr));
}

// bf16 mma (attention)
__device__ __forceinline__ void mma16816(float* c, const uint32_t* a,
                                         const uint32_t* b) {
    asm volatile(
        "mma.sync.aligned.m16n8k16.row.col.f32.bf16.bf16.f32 "
        "{%0,%1,%2,%3}, {%4,%5,%6,%7}, {%8,%9}, {%0,%1,%2,%3};"
        : "+f"(c[0]), "+f"(c[1]), "+f"(c[2]), "+f"(c[3])
        : "r"(a[0]), "r"(a[1]), "r"(a[2]), "r"(a[3]), "r"(b[0]), "r"(b[1]));
}

// fp16 mma (projection GEMMs)
__device__ __forceinline__ void mma16816h(float* c, const uint32_t* a,
                                          const uint32_t* b) {
    asm volatile(
        "mma.sync.aligned.m16n8k16.row.col.f32.f16.f16.f32 "
        "{%0,%1,%2,%3}, {%4,%5,%6,%7}, {%8,%9}, {%0,%1,%2,%3};"
        : "+f"(c[0]), "+f"(c[1]), "+f"(c[2]), "+f"(c[3])
        : "r"(a[0]), "r"(a[1]), "r"(a[2]), "r"(a[3]), "r"(b[0]), "r"(b[1]));
}

// fp32 pair -> bf16x2 hi + lo (q/k/v for attention)
__device__ __forceinline__ void split2(float x, float y, uint32_t& hi, uint32_t& lo) {
    __nv_bfloat16 hx = __float2bfloat16_rn(x);
    __nv_bfloat16 hy = __float2bfloat16_rn(y);
    __nv_bfloat16 lx = __float2bfloat16_rn(x - __bfloat162float(hx));
    __nv_bfloat16 ly = __float2bfloat16_rn(y - __bfloat162float(hy));
    __nv_bfloat162 H = __halves2bfloat162(hx, hy);
    __nv_bfloat162 L = __halves2bfloat162(lx, ly);
    hi = *reinterpret_cast<uint32_t*>(&H);
    lo = *reinterpret_cast<uint32_t*>(&L);
}

// fp32 pair -> fp16x2 hi + lo (ctx for out GEMM)
__device__ __forceinline__ void split2h(float x, float y, uint32_t& hi, uint32_t& lo) {
    __half hx = __float2half_rn(x);
    __half hy = __float2half_rn(y);
    __half lx = __float2half_rn(x - __half2float(hx));
    __half ly = __float2half_rn(y - __half2float(hy));
    __half2 H = __halves2half2(hx, hy);
    __half2 L = __halves2half2(lx, ly);
    hi = *reinterpret_cast<uint32_t*>(&H);
    lo = *reinterpret_cast<uint32_t*>(&L);
}

// ---------------- fused conversion: x -> fp16 hi/lo, weights -> fp16 -------
#define NX8 (ELEMS / 8)    // 2^20
#define NW8 (WELEMS / 8)   // 2^17

__global__ __launch_bounds__(256) void cvt_all(const float* __restrict__ x,
                                               const float* __restrict__ Wq,
                                               const float* __restrict__ Wk,
                                               const float* __restrict__ Wv,
                                               const float* __restrict__ Wo) {
    int i = blockIdx.x * blockDim.x + threadIdx.x;
    if (i < (int)NX8) {
        const float4* s4 = (const float4*)x;
        float4 a = s4[2 * i], b = s4[2 * i + 1];
        float v[8] = {a.x, a.y, a.z, a.w, b.x, b.y, b.z, b.w};
        uint4 hp, lp;
        __half* hs = (__half*)&hp;
        __half* ls = (__half*)&lp;
#pragma unroll
        for (int j = 0; j < 8; ++j) {
            __half h = __float2half_rn(v[j]);
            hs[j] = h;
            ls[j] = __float2half_rn(v[j] - __half2float(h));
        }
        ((uint4*)g_xh)[i] = hp;
        ((uint4*)g_xl)[i] = lp;
    } else {
        int j = i - (int)NX8;
        int w = j >> 17;
        int off = j & (int)(NW8 - 1);
        const float* src;
        __half* dst;
        if (w == 0)      { src = Wq; dst = g_wq16; }
        else if (w == 1) { src = Wk; dst = g_wk16; }
        else if (w == 2) { src = Wv; dst = g_wv16; }
        else             { src = Wo; dst = g_wo16; }
        const float4* s4 = (const float4*)src;
        float4 a = s4[2 * off], b = s4[2 * off + 1];
        float v[8] = {a.x, a.y, a.z, a.w, b.x, b.y, b.z, b.w};
        uint4 hp;
        __half* hs = (__half*)&hp;
#pragma unroll
        for (int q = 0; q < 8; ++q) hs[q] = __float2half_rn(v[q]);
        ((uint4*)dst)[off] = hp;
    }
}

// ---------------- fp16 2-pass GEMM: C = (Ah+Al)@Bh^T (+bias) ---------------
// R15: 3 smem tiles (Ah, Al, Bh), 64B pitch + XOR swizzle, 4 stages,
// ONE barrier per chunk, 3-chunk prefetch, 2 CTAs/SM (2*98304 = 196608B).
#define BK     32
#define NCHUNK (DMODEL / BK)        // 32
#define OPT_BYTES (128 * 64)        // 8192 per operand tile
#define STAGE_BYTES (3 * OPT_BYTES) // 24576
#define NSTAGE 4
#define GEMM_SMEM (NSTAGE * STAGE_BYTES) // 98304

__device__ __forceinline__ uint32_t swz(uint32_t row, uint32_t col16) {
    return row * 64 + ((col16 ^ ((row >> 1) & 3)) << 4);
}

__device__ __forceinline__ void load_chunk(uint32_t stb,
                                           const __half* Ahi,
                                           const __half* Alo,
                                           const __half* Bh,
                                           int bm, int bn, int k0, int tid) {
    const __half* srcs[3] = {Ahi, Alo, Bh};
#pragma unroll
    for (int t = 0; t < 3; ++t) {
        const __half* src = srcs[t];
        const int rowbase = (t < 2) ? bm : bn;
        const uint32_t tb = stb + t * OPT_BYTES;
#pragma unroll
        for (int j = 0; j < 2; ++j) {
            int u = tid + j * 256;
            int r = u >> 2, seg = u & 3;
            uint32_t dst = tb + swz((uint32_t)r, (uint32_t)seg);
            const void* g = src + (size_t)(rowbase + r) * DMODEL + k0 + seg * 8;
            cp16(dst, g);
        }
    }
    asm volatile("cp.async.commit_group;" ::: "memory");
}

template <bool SPLITOUT, bool HASBIAS>
__device__ __forceinline__ void gemm_core(const __half* __restrict__ Ahi,
                                          const __half* __restrict__ Alo,
                                          const __half* __restrict__ Bh,
                                          const float* __restrict__ bias,
                                          float* __restrict__ C,
                                          __nv_bfloat16* __restrict__ Chi,
                                          __nv_bfloat16* __restrict__ Clo,
                                          float scale) {
    const int tid = threadIdx.x;
    const int lane = tid & 31, warp = tid >> 5;
    const int wm = warp >> 2, wn = warp & 3;
    const int bm = blockIdx.x * 128, bn = blockIdx.y * 128;
    const uint32_t sb = s2u(dynsmem);

    const uint32_t a_row = lane & 15;
    const uint32_t a_c16 = (uint32_t)(lane >> 4);
    const uint32_t b_row = (lane & 7) + ((lane & 16) >> 1);
    const uint32_t b_c16 = (uint32_t)((lane >> 3) & 1);

    float acc[4][4][4];
#pragma unroll
    for (int i = 0; i < 4; ++i)
#pragma unroll
        for (int j = 0; j < 4; ++j)
#pragma unroll
            for (int q = 0; q < 4; ++q) acc[i][j][q] = 0.f;

    load_chunk(sb,                   Ahi, Alo, Bh, bm, bn, 0,      tid);
    load_chunk(sb + STAGE_BYTES,     Ahi, Alo, Bh, bm, bn, BK,     tid);
    load_chunk(sb + 2 * STAGE_BYTES, Ahi, Alo, Bh, bm, bn, 2 * BK, tid);

    for (int k = 0; k < NCHUNK; ++k) {
        const uint32_t stb = sb + (uint32_t)(k % NSTAGE) * STAGE_BYTES;
        if (k >= NCHUNK - 1)
            asm volatile("cp.async.wait_group 0;" ::: "memory");
        else if (k == NCHUNK - 2)
            asm volatile("cp.async.wait_group 1;" ::: "memory");
        else
            asm volatile("cp.async.wait_group 2;" ::: "memory");
        __syncthreads();   // chunk k visible AND compute k-1 done on all warps
        // overwrite stage (k+3)%4 == (k-1)%4 — safe after barrier
        if (k + 3 < NCHUNK)
            load_chunk(sb + (uint32_t)((k + 3) % NSTAGE) * STAGE_BYTES,
                       Ahi, Alo, Bh, bm, bn, (k + 3) * BK, tid);

#pragma unroll
        for (int ks = 0; ks < 2; ++ks) {
            uint32_t ah[4][4], al[4][4], bh[4][2];
#pragma unroll
            for (int mt = 0; mt < 4; ++mt) {
                uint32_t row = (uint32_t)(wm * 64 + mt * 16) + a_row;
                uint32_t ra = stb + swz(row, (uint32_t)(ks * 2) + a_c16);
                ldsm_x4(ah[mt], ra);
                ldsm_x4(al[mt], ra + OPT_BYTES);
            }
#pragma unroll
            for (int p = 0; p < 2; ++p) {
                uint32_t row = (uint32_t)(wn * 32 + p * 16) + b_row;
                uint32_t rb = stb + 2 * OPT_BYTES
                            + swz(row, (uint32_t)(ks * 2) + b_c16);
                uint32_t t[4];
                ldsm_x4(t, rb);
                bh[p * 2 + 0][0] = t[0]; bh[p * 2 + 0][1] = t[1];
                bh[p * 2 + 1][0] = t[2]; bh[p * 2 + 1][1] = t[3];
            }
#pragma unroll
            for (int mt = 0; mt < 4; ++mt)
#pragma unroll
                for (int nt = 0; nt < 4; ++nt)
                    mma16816h(acc[mt][nt], ah[mt], bh[nt]);
#pragma unroll
            for (int mt = 0; mt < 4; ++mt)
#pragma unroll
                for (int nt = 0; nt < 4; ++nt)
                    mma16816h(acc[mt][nt], al[mt], bh[nt]);
        }
    }

    const int rbase = bm + wm * 64 + (lane >> 2);
    const int cbase = bn + wn * 32 + (lane & 3) * 2;
#pragma unroll
    for (int mt = 0; mt < 4; ++mt)
#pragma unroll
        for (int nt = 0; nt < 4; ++nt) {
            const int row = rbase + mt * 16;
            const int col = cbase + nt * 8;
            if (SPLITOUT) {
                uint32_t hh, ll;
                split2(acc[mt][nt][0] * scale, acc[mt][nt][1] * scale, hh, ll);
                *(uint32_t*)(Chi + (size_t)row * DMODEL + col) = hh;
                *(uint32_t*)(Clo + (size_t)row * DMODEL + col) = ll;
                split2(acc[mt][nt][2] * scale, acc[mt][nt][3] * scale, hh, ll);
                *(uint32_t*)(Chi + (size_t)(row + 8) * DMODEL + col) = hh;
                *(uint32_t*)(Clo + (size_t)(row + 8) * DMODEL + col) = ll;
            } else {
                float2 v0 = make_float2(acc[mt][nt][0], acc[mt][nt][1]);
                float2 v1 = make_float2(acc[mt][nt][2], acc[mt][nt][3]);
                if (HASBIAS) {
                    float2 bb = *(const float2*)(bias + col);
                    v0.x += bb.x; v0.y += bb.y;
                    v1.x += bb.x; v1.y += bb.y;
                }
                *(float2*)(C + (size_t)row * DMODEL + col) = v0;
                *(float2*)(C + (size_t)(row + 8) * DMODEL + col) = v1;
            }
        }
}

__global__ __launch_bounds__(256, 2) void qkv_gemm_tc() {
    const __half* bh;
    __nv_bfloat16 *ohi, *olo;
    float scale;
    if (blockIdx.z == 0)      { bh = g_wq16; ohi = g_qhi; olo = g_qlo; scale = 0.125f; }
    else if (blockIdx.z == 1) { bh = g_wk16; ohi = g_khi; olo = g_klo; scale = 1.f; }
    else                      { bh = g_wv16; ohi = g_vhi; olo = g_vlo; scale = 1.f; }
    gemm_core<true, false>(g_xh, g_xl, bh, nullptr, nullptr, ohi, olo, scale);
}

__global__ __launch_bounds__(256, 2) void out_gemm_tc(const float* __restrict__ bo,
                                                      float* __restrict__ out) {
    gemm_core<false, true>(g_ch, g_cl, g_wo16, bo, out, nullptr, nullptr, 1.f);
}

// ---------------- split-bf16 mma flash attention (validated R14) ------------
#define APITCH 144
#define SQLO_OFF 18432
#define KV_BASE  36864
#define KV_STAGE 36864
#define ATTN_SMEM (KV_BASE + 3 * KV_STAGE)   // 147456

__device__ __forceinline__ void load_kv(uint32_t sb, int st, int kt,
                                        size_t trow0, int hc, int tid) {
    const uint32_t base = sb + KV_BASE + (uint32_t)st * KV_STAGE;
    const __nv_bfloat16* srcs[4] = {g_khi, g_klo, g_vhi, g_vlo};
#pragma unroll
    for (int i = 0; i < 8; ++i) {
        int u = tid + i * 256;
        int arr = u >> 9, r = (u >> 3) & 63, seg = u & 7;
        const void* src = srcs[arr] + (trow0 + (size_t)kt * 64 + r) * DMODEL
                        + hc + seg * 8;
        cp16(base + arr * 9216 + r * APITCH + seg * 16, src);
    }
    asm volatile("cp.async.commit_group;" ::: "memory");
}

__global__ __launch_bounds__(256, 1) void attn_mma() {
    const int qt = (int)gridDim.x - 1 - (int)blockIdx.x;  // heavy tiles first
    const int h = blockIdx.y, b = blockIdx.z;
    const int tid = threadIdx.x, lane = tid & 31, w = tid >> 5;
    const uint32_t sb = s2u(dynsmem);
    const int nkt = 2 * qt + 2;
    const size_t trow0 = (size_t)b * TSEQ;
    const int hc = h * DKH;

#pragma unroll
    for (int i = 0; i < 8; ++i) {
        int u = tid + i * 256;
        int arr = u >> 10, r = (u >> 3) & 127, seg = u & 7;
        const void* src = (arr ? g_qlo : g_qhi)
            + (trow0 + (size_t)qt * 128 + r) * DMODEL + hc + seg * 8;
        cp16(sb + (arr ? SQLO_OFF : 0) + r * APITCH + seg * 16, src);
    }
    asm volatile("cp.async.commit_group;" ::: "memory");
    load_kv(sb, 0, 0, trow0, hc, tid);
    load_kv(sb, 1, 1, trow0, hc, tid);

    const int a_row = lane & 15;
    const int a_ch2 = ((lane >> 4) << 3) * 2;
    const int b_row = (lane & 7) + ((lane & 16) >> 1);
    const int b_ch2 = (lane & 8) * 2;
    const int rg0 = qt * 128 + 16 * w + (lane >> 2);
    const int cg0 = 2 * (lane & 3);

    asm volatile("cp.async.wait_group 2;" ::: "memory");
    __syncthreads();
    uint32_t qh[4][4], ql[4][4];
#pragma unroll
    for (int t = 0; t < 4; ++t) {
        uint32_t ra = sb + (uint32_t)(16 * w + a_row) * APITCH + t * 32 + a_ch2;
        ldsm_x4(qh[t], ra);
        ldsm_x4(ql[t], ra + SQLO_OFF);
    }

    float m0 = -1e30f, m1 = -1e30f, l0 = 0.f, l1 = 0.f;
    float o[8][4];
#pragma unroll
    for (int j = 0; j < 8; ++j)
#pragma unroll
        for (int q = 0; q < 4; ++q) o[j][q] = 0.f;

    for (int kt = 0; kt < nkt; ++kt) {
        if (kt == nkt - 1)
            asm volatile("cp.async.wait_group 0;" ::: "memory");
        else
            asm volatile("cp.async.wait_group 1;" ::: "memory");
        __syncthreads();
        const uint32_t kvb = sb + KV_BASE + (uint32_t)(kt % 3) * KV_STAGE;

        float s[8][4];
#pragma unroll
        for (int j = 0; j < 8; ++j)
#pragma unroll
            for (int q = 0; q < 4; ++q) s[j][q] = 0.f;

#pragma unroll
        for (int t = 0; t < 4; ++t) {
            uint32_t th[4][4], tl[4][4];
#pragma unroll
            for (int p = 0; p < 4; ++p) {
                uint32_t rb = kvb + (uint32_t)(p * 16 + b_row) * APITCH + t * 32 + b_ch2;
                ldsm_x4(th[p], rb);
                ldsm_x4(tl[p], rb + 9216);
            }
#pragma unroll
            for (int p = 0; p < 4; ++p) {
                mma16816(s[2 * p],     qh[t], &th[p][0]);
                mma16816(s[2 * p + 1], qh[t], &th[p][2]);
            }
#pragma unroll
            for (int p = 0; p < 4; ++p) {
                mma16816(s[2 * p],     qh[t], &tl[p][0]);
                mma16816(s[2 * p + 1], qh[t], &tl[p][2]);
            }
#pragma unroll
            for (int p = 0; p < 4; ++p) {
                mma16816(s[2 * p],     ql[t], &th[p][0]);
                mma16816(s[2 * p + 1], ql[t], &th[p][2]);
            }
        }

        if (kt >= nkt - 2) {
            const int cb = kt * 64 + cg0;
#pragma unroll
            for (int j = 0; j < 8; ++j) {
                int c0 = cb + 8 * j;
                if (c0     > rg0)     s[j][0] = -1e9f;
                if (c0 + 1 > rg0)     s[j][1] = -1e9f;
                if (c0     > rg0 + 8) s[j][2] = -1e9f;
                if (c0 + 1 > rg0 + 8) s[j][3] = -1e9f;
            }
        }

        float tm0 = -1e30f, tm1 = -1e30f;
#pragma unroll
        for (int j = 0; j < 8; ++j) {
            tm0 = fmaxf(tm0, fmaxf(s[j][0], s[j][1]));
            tm1 = fmaxf(tm1, fmaxf(s[j][2], s[j][3]));
        }
        tm0 = fmaxf(tm0, __shfl_xor_sync(0xffffffffu, tm0, 1));
        tm0 = fmaxf(tm0, __shfl_xor_sync(0xffffffffu, tm0, 2));
        tm1 = fmaxf(tm1, __shfl_xor_sync(0xffffffffu, tm1, 1));
        tm1 = fmaxf(tm1, __shfl_xor_sync(0xffffffffu, tm1, 2));
        const float mn0 = fmaxf(m0, tm0), mn1 = fmaxf(m1, tm1);
        const float sc0 = __expf(m0 - mn0), sc1 = __expf(m1 - mn1);
        float sum0 = 0.f, sum1 = 0.f;
#pragma unroll
        for (int j = 0; j < 8; ++j) {
            s[j][0] = __expf(s[j][0] - mn0);
            s[j][1] = __expf(s[j][1] - mn0);
            s[j][2] = __expf(s[j][2] - mn1);
            s[j][3] = __expf(s[j][3] - mn1);
            sum0 += s[j][0] + s[j][1];
            sum1 += s[j][2] + s[j][3];
        }
        sum0 += __shfl_xor_sync(0xffffffffu, sum0, 1);
        sum0 += __shfl_xor_sync(0xffffffffu, sum0, 2);
        sum1 += __shfl_xor_sync(0xffffffffu, sum1, 1);
        sum1 += __shfl_xor_sync(0xffffffffu, sum1, 2);
        l0 = l0 * sc0 + sum0;
        l1 = l1 * sc1 + sum1;
        m0 = mn0; m1 = mn1;
#pragma unroll
        for (int j = 0; j < 8; ++j) {
            o[j][0] *= sc0; o[j][1] *= sc0;
            o[j][2] *= sc1; o[j][3] *= sc1;
        }

#pragma unroll
        for (int t = 0; t < 4; ++t) {
            uint32_t phi[4], plo[4];
            split2(s[2 * t][0],     s[2 * t][1],     phi[0], plo[0]);
            split2(s[2 * t][2],     s[2 * t][3],     phi[1], plo[1]);
            split2(s[2 * t + 1][0], s[2 * t + 1][1], phi[2], plo[2]);
            split2(s[2 * t + 1][2], s[2 * t + 1][3], phi[3], plo[3]);
            uint32_t vh[4][4], vl[4][4];
#pragma unroll
            for (int np = 0; np < 4; ++np) {
                uint32_t rv = kvb + 18432
                            + (uint32_t)(t * 16 + (lane & 15)) * APITCH
                            + (uint32_t)(np * 16 + ((lane >> 4) << 3)) * 2;
                ldsm_x4_t(vh[np], rv);
                ldsm_x4_t(vl[np], rv + 9216);
            }
#pragma unroll
            for (int np = 0; np < 4; ++np) {
                mma16816(o[2 * np],     phi, &vh[np][0]);
                mma16816(o[2 * np + 1], phi, &vh[np][2]);
            }
#pragma unroll
            for (int np = 0; np < 4; ++np) {
                mma16816(o[2 * np],     phi, &vl[np][0]);
                mma16816(o[2 * np + 1], phi, &vl[np][2]);
            }
#pragma unroll
            for (int np = 0; np < 4; ++np) {
                mma16816(o[2 * np],     plo, &vh[np][0]);
                mma16816(o[2 * np + 1], plo, &vh[np][2]);
            }
        }

        if (kt + 2 < nkt)
            load_kv(sb, (kt + 2) % 3, kt + 2, trow0, hc, tid);
    }

    // epilogue: ctx = O / l, written as fp16 hi/lo for the fp16 out GEMM
    const float i0 = 1.f / l0, i1 = 1.f / l1;
    const size_t r0t = trow0 + (size_t)qt * 128 + 16 * w + (lane >> 2);
#pragma unroll
    for (int j = 0; j < 8; ++j) {
        const int col = hc + 8 * j + cg0;
        uint32_t hh, ll;
        split2h(o[j][0] * i0, o[j][1] * i0, hh, ll);
        *(uint32_t*)(g_ch + r0t * DMODEL + col) = hh;
        *(uint32_t*)(g_cl + r0t * DMODEL + col) = ll;
        split2h(o[j][2] * i1, o[j][3] * i1, hh, ll);
        *(uint32_t*)(g_ch + (r0t + 8) * DMODEL + col) = hh;
        *(uint32_t*)(g_cl + (r0t + 8) * DMODEL + col) = ll;
    }
}

// ---------------------------------------------------------------------------
extern "C" void kernel_launch(void* const* d_in, const int* in_sizes, int n_in,
                              void* d_out, int out_size) {
    (void)in_sizes; (void)n_in; (void)out_size;
    const float* x  = (const float*)d_in[0];
    // d_in[1]: causal mask — handled analytically.
    const float* Wq = (const float*)d_in[2];
    const float* Wk = (const float*)d_in[3];
    const float* Wv = (const float*)d_in[4];
    const float* Wo = (const float*)d_in[5];
    const float* bo = (const float*)d_in[6];
    float* out = (float*)d_out;

    cudaFuncSetAttribute(qkv_gemm_tc, cudaFuncAttributeMaxDynamicSharedMemorySize, GEMM_SMEM);
    cudaFuncSetAttribute(out_gemm_tc, cudaFuncAttributeMaxDynamicSharedMemorySize, GEMM_SMEM);
    cudaFuncSetAttribute(attn_mma,    cudaFuncAttributeMaxDynamicSharedMemorySize, ATTN_SMEM);

    const int ntot8 = (int)(NX8 + 4 * NW8);
    cvt_all<<<ntot8 / 256, 256>>>(x, Wq, Wk, Wv, Wo);

    qkv_gemm_tc<<<dim3(MROWS / 128, DMODEL / 128, 3), 256, GEMM_SMEM>>>();
    attn_mma<<<dim3(TSEQ / 128, NHEADS, BATCH), 256, ATTN_SMEM>>>();
    out_gemm_tc<<<dim3(MROWS / 128, DMODEL / 128, 1), 256, GEMM_SMEM>>>(bo, out);
}

// round 17
// speedup vs baseline: 4.6748x; 1.1701x over previous
#include <cuda_runtime.h>
#include <cuda_bf16.h>
#include <cuda_fp16.h>
#include <cstdint>

#define BATCH  4
#define TSEQ   2048
#define DMODEL 1024
#define NHEADS 16
#define DKH    64
#define MROWS  (BATCH * TSEQ)                 // 8192
#define ELEMS  ((size_t)MROWS * DMODEL)       // 8388608
#define WELEMS ((size_t)DMODEL * DMODEL)      // 1048576

// ---------------- device scratch (no runtime allocation) -------------------
// attention operands (fp16): Q split hi/lo, K/V single
__device__ __half g_qh16[ELEMS], g_ql16[ELEMS];
__device__ __half g_k16[ELEMS], g_v16[ELEMS];
// projection-GEMM operands: fp16 (A split hi/lo, W single)
__device__ __half g_xh[ELEMS], g_xl[ELEMS];
__device__ __half g_ch[ELEMS], g_cl[ELEMS];
__device__ __half g_wq16[WELEMS], g_wk16[WELEMS], g_wv16[WELEMS], g_wo16[WELEMS];

extern __shared__ __align__(1024) char dynsmem[];

__device__ __forceinline__ uint32_t s2u(const void* p) {
    uint32_t a;
    asm("{ .reg .u64 t; cvta.to.shared.u64 t, %1; cvt.u32.u64 %0, t; }"
        : "=r"(a) : "l"(p));
    return a;
}

__device__ __forceinline__ void cp16(uint32_t dst, const void* src) {
    asm volatile("cp.async.cg.shared.global [%0], [%1], 16;"
                 :: "r"(dst), "l"(src));
}

__device__ __forceinline__ void ldsm_x4(uint32_t* r, uint32_t addr) {
    asm volatile("ldmatrix.sync.aligned.m8n8.x4.shared.b16 {%0,%1,%2,%3}, [%4];"
                 : "=r"(r[0]), "=r"(r[1]), "=r"(r[2]), "=r"(r[3]) : "r"(addr));
}

__device__ __forceinline__ void ldsm_x4_t(uint32_t* r, uint32_t addr) {
    asm volatile("ldmatrix.sync.aligned.m8n8.x4.trans.shared.b16 {%0,%1,%2,%3}, [%4];"
                 : "=r"(r[0]), "=r"(r[1]), "=r"(r[2]), "=r"(r[3]) : "r"(addr));
}

// fp16 mma
__device__ __forceinline__ void mma16816h(float* c, const uint32_t* a,
                                          const uint32_t* b) {
    asm volatile(
        "mma.sync.aligned.m16n8k16.row.col.f32.f16.f16.f32 "
        "{%0,%1,%2,%3}, {%4,%5,%6,%7}, {%8,%9}, {%0,%1,%2,%3};"
        : "+f"(c[0]), "+f"(c[1]), "+f"(c[2]), "+f"(c[3])
        : "r"(a[0]), "r"(a[1]), "r"(a[2]), "r"(a[3]), "r"(b[0]), "r"(b[1]));
}

// fp32 pair -> fp16x2 hi + lo
__device__ __forceinline__ void split2h(float x, float y, uint32_t& hi, uint32_t& lo) {
    __half hx = __float2half_rn(x);
    __half hy = __float2half_rn(y);
    __half lx = __float2half_rn(x - __half2float(hx));
    __half ly = __float2half_rn(y - __half2float(hy));
    __half2 H = __halves2half2(hx, hy);
    __half2 L = __halves2half2(lx, ly);
    hi = *reinterpret_cast<uint32_t*>(&H);
    lo = *reinterpret_cast<uint32_t*>(&L);
}

__device__ __forceinline__ uint32_t pack2h(float x, float y) {
    __half2 H = __halves2half2(__float2half_rn(x), __float2half_rn(y));
    return *reinterpret_cast<uint32_t*>(&H);
}

// ---------------- fused conversion: x -> fp16 hi/lo, weights -> fp16 -------
#define NX8 (ELEMS / 8)    // 2^20
#define NW8 (WELEMS / 8)   // 2^17

__global__ __launch_bounds__(256) void cvt_all(const float* __restrict__ x,
                                               const float* __restrict__ Wq,
                                               const float* __restrict__ Wk,
                                               const float* __restrict__ Wv,
                                               const float* __restrict__ Wo) {
    int i = blockIdx.x * blockDim.x + threadIdx.x;
    if (i < (int)NX8) {
        const float4* s4 = (const float4*)x;
        float4 a = s4[2 * i], b = s4[2 * i + 1];
        float v[8] = {a.x, a.y, a.z, a.w, b.x, b.y, b.z, b.w};
        uint4 hp, lp;
        __half* hs = (__half*)&hp;
        __half* ls = (__half*)&lp;
#pragma unroll
        for (int j = 0; j < 8; ++j) {
            __half h = __float2half_rn(v[j]);
            hs[j] = h;
            ls[j] = __float2half_rn(v[j] - __half2float(h));
        }
        ((uint4*)g_xh)[i] = hp;
        ((uint4*)g_xl)[i] = lp;
    } else {
        int j = i - (int)NX8;
        int w = j >> 17;
        int off = j & (int)(NW8 - 1);
        const float* src;
        __half* dst;
        if (w == 0)      { src = Wq; dst = g_wq16; }
        else if (w == 1) { src = Wk; dst = g_wk16; }
        else if (w == 2) { src = Wv; dst = g_wv16; }
        else             { src = Wo; dst = g_wo16; }
        const float4* s4 = (const float4*)src;
        float4 a = s4[2 * off], b = s4[2 * off + 1];
        float v[8] = {a.x, a.y, a.z, a.w, b.x, b.y, b.z, b.w};
        uint4 hp;
        __half* hs = (__half*)&hp;
#pragma unroll
        for (int q = 0; q < 8; ++q) hs[q] = __float2half_rn(v[q]);
        ((uint4*)dst)[off] = hp;
    }
}

// ---------------- fp16 2-pass GEMM: C = (Ah+Al)@Bh^T (+bias) ---------------
// OUTMODE: 0 = fp32 + bias (final out), 1 = fp16 hi/lo split, 2 = fp16 single
#define BK     32
#define NCHUNK (DMODEL / BK)        // 32
#define OPT_BYTES (128 * 64)        // 8192 per operand tile
#define STAGE_BYTES (3 * OPT_BYTES) // 24576
#define NSTAGE 4
#define GEMM_SMEM (NSTAGE * STAGE_BYTES) // 98304

__device__ __forceinline__ uint32_t swz(uint32_t row, uint32_t col16) {
    return row * 64 + ((col16 ^ ((row >> 1) & 3)) << 4);
}

__device__ __forceinline__ void load_chunk(uint32_t stb,
                                           const __half* Ahi,
                                           const __half* Alo,
                                           const __half* Bh,
                                           int bm, int bn, int k0, int tid) {
    const __half* srcs[3] = {Ahi, Alo, Bh};
#pragma unroll
    for (int t = 0; t < 3; ++t) {
        const __half* src = srcs[t];
        const int rowbase = (t < 2) ? bm : bn;
        const uint32_t tb = stb + t * OPT_BYTES;
#pragma unroll
        for (int j = 0; j < 2; ++j) {
            int u = tid + j * 256;
            int r = u >> 2, seg = u & 3;
            uint32_t dst = tb + swz((uint32_t)r, (uint32_t)seg);
            const void* g = src + (size_t)(rowbase + r) * DMODEL + k0 + seg * 8;
            cp16(dst, g);
        }
    }
    asm volatile("cp.async.commit_group;" ::: "memory");
}

template <int OUTMODE>
__device__ __forceinline__ void gemm_core(const __half* __restrict__ Ahi,
                                          const __half* __restrict__ Alo,
                                          const __half* __restrict__ Bh,
                                          const float* __restrict__ bias,
                                          float* __restrict__ C,
                                          __half* __restrict__ Chi,
                                          __half* __restrict__ Clo,
                                          float scale) {
    const int tid = threadIdx.x;
    const int lane = tid & 31, warp = tid >> 5;
    const int wm = warp >> 2, wn = warp & 3;
    const int bm = blockIdx.x * 128, bn = blockIdx.y * 128;
    const uint32_t sb = s2u(dynsmem);

    const uint32_t a_row = lane & 15;
    const uint32_t a_c16 = (uint32_t)(lane >> 4);
    const uint32_t b_row = (lane & 7) + ((lane & 16) >> 1);
    const uint32_t b_c16 = (uint32_t)((lane >> 3) & 1);

    float acc[4][4][4];
#pragma unroll
    for (int i = 0; i < 4; ++i)
#pragma unroll
        for (int j = 0; j < 4; ++j)
#pragma unroll
            for (int q = 0; q < 4; ++q) acc[i][j][q] = 0.f;

    load_chunk(sb,                   Ahi, Alo, Bh, bm, bn, 0,      tid);
    load_chunk(sb + STAGE_BYTES,     Ahi, Alo, Bh, bm, bn, BK,     tid);
    load_chunk(sb + 2 * STAGE_BYTES, Ahi, Alo, Bh, bm, bn, 2 * BK, tid);

    for (int k = 0; k < NCHUNK; ++k) {
        const uint32_t stb = sb + (uint32_t)(k % NSTAGE) * STAGE_BYTES;
        if (k >= NCHUNK - 1)
            asm volatile("cp.async.wait_group 0;" ::: "memory");
        else if (k == NCHUNK - 2)
            asm volatile("cp.async.wait_group 1;" ::: "memory");
        else
            asm volatile("cp.async.wait_group 2;" ::: "memory");
        __syncthreads();
        if (k + 3 < NCHUNK)
            load_chunk(sb + (uint32_t)((k + 3) % NSTAGE) * STAGE_BYTES,
                       Ahi, Alo, Bh, bm, bn, (k + 3) * BK, tid);

#pragma unroll
        for (int ks = 0; ks < 2; ++ks) {
            uint32_t ah[4][4], al[4][4], bh[4][2];
#pragma unroll
            for (int mt = 0; mt < 4; ++mt) {
                uint32_t row = (uint32_t)(wm * 64 + mt * 16) + a_row;
                uint32_t ra = stb + swz(row, (uint32_t)(ks * 2) + a_c16);
                ldsm_x4(ah[mt], ra);
                ldsm_x4(al[mt], ra + OPT_BYTES);
            }
#pragma unroll
            for (int p = 0; p < 2; ++p) {
                uint32_t row = (uint32_t)(wn * 32 + p * 16) + b_row;
                uint32_t rb = stb + 2 * OPT_BYTES
                            + swz(row, (uint32_t)(ks * 2) + b_c16);
                uint32_t t[4];
                ldsm_x4(t, rb);
                bh[p * 2 + 0][0] = t[0]; bh[p * 2 + 0][1] = t[1];
                bh[p * 2 + 1][0] = t[2]; bh[p * 2 + 1][1] = t[3];
            }
#pragma unroll
            for (int mt = 0; mt < 4; ++mt)
#pragma unroll
                for (int nt = 0; nt < 4; ++nt)
                    mma16816h(acc[mt][nt], ah[mt], bh[nt]);
#pragma unroll
            for (int mt = 0; mt < 4; ++mt)
#pragma unroll
                for (int nt = 0; nt < 4; ++nt)
                    mma16816h(acc[mt][nt], al[mt], bh[nt]);
        }
    }

    const int rbase = bm + wm * 64 + (lane >> 2);
    const int cbase = bn + wn * 32 + (lane & 3) * 2;
#pragma unroll
    for (int mt = 0; mt < 4; ++mt)
#pragma unroll
        for (int nt = 0; nt < 4; ++nt) {
            const int row = rbase + mt * 16;
            const int col = cbase + nt * 8;
            if (OUTMODE == 1) {
                uint32_t hh, ll;
                split2h(acc[mt][nt][0] * scale, acc[mt][nt][1] * scale, hh, ll);
                *(uint32_t*)(Chi + (size_t)row * DMODEL + col) = hh;
                *(uint32_t*)(Clo + (size_t)row * DMODEL + col) = ll;
                split2h(acc[mt][nt][2] * scale, acc[mt][nt][3] * scale, hh, ll);
                *(uint32_t*)(Chi + (size_t)(row + 8) * DMODEL + col) = hh;
                *(uint32_t*)(Clo + (size_t)(row + 8) * DMODEL + col) = ll;
            } else if (OUTMODE == 2) {
                *(uint32_t*)(Chi + (size_t)row * DMODEL + col) =
                    pack2h(acc[mt][nt][0], acc[mt][nt][1]);
                *(uint32_t*)(Chi + (size_t)(row + 8) * DMODEL + col) =
                    pack2h(acc[mt][nt][2], acc[mt][nt][3]);
            } else {
                float2 bb = *(const float2*)(bias + col);
                float2 v0 = make_float2(acc[mt][nt][0] + bb.x, acc[mt][nt][1] + bb.y);
                float2 v1 = make_float2(acc[mt][nt][2] + bb.x, acc[mt][nt][3] + bb.y);
                *(float2*)(C + (size_t)row * DMODEL + col) = v0;
                *(float2*)(C + (size_t)(row + 8) * DMODEL + col) = v1;
            }
        }
}

__global__ __launch_bounds__(256, 2) void qkv_gemm_tc() {
    if (blockIdx.z == 0)
        gemm_core<1>(g_xh, g_xl, g_wq16, nullptr, nullptr, g_qh16, g_ql16, 0.125f);
    else if (blockIdx.z == 1)
        gemm_core<2>(g_xh, g_xl, g_wk16, nullptr, nullptr, g_k16, nullptr, 1.f);
    else
        gemm_core<2>(g_xh, g_xl, g_wv16, nullptr, nullptr, g_v16, nullptr, 1.f);
}

__global__ __launch_bounds__(256, 2) void out_gemm_tc(const float* __restrict__ bo,
                                                      float* __restrict__ out) {
    gemm_core<0>(g_ch, g_cl, g_wo16, bo, out, nullptr, nullptr, 1.f);
}

// ---------------- fp16 2-pass mma flash attention ---------------------------
// Q split hi/lo; K, V single fp16. KV stage = K tile + V tile = 18432 B.
#define APITCH 144
#define SQLO_OFF 18432
#define KV_BASE  36864
#define KV_STAGE 18432
#define ATTN_SMEM (KV_BASE + 3 * KV_STAGE)   // 92160

__device__ __forceinline__ void load_kv(uint32_t sb, int st, int kt,
                                        size_t trow0, int hc, int tid) {
    const uint32_t base = sb + KV_BASE + (uint32_t)st * KV_STAGE;
#pragma unroll
    for (int i = 0; i < 4; ++i) {
        int u = tid + i * 256;                 // 0..1023
        int arr = u >> 9, r = (u >> 3) & 63, seg = u & 7;
        const __half* src = (arr ? g_v16 : g_k16);
        const void* g = src + (trow0 + (size_t)kt * 64 + r) * DMODEL + hc + seg * 8;
        cp16(base + arr * 9216 + r * APITCH + seg * 16, g);
    }
    asm volatile("cp.async.commit_group;" ::: "memory");
}

__global__ __launch_bounds__(256, 1) void attn_mma() {
    const int qt = (int)gridDim.x - 1 - (int)blockIdx.x;  // heavy tiles first
    const int h = blockIdx.y, b = blockIdx.z;
    const int tid = threadIdx.x, lane = tid & 31, w = tid >> 5;
    const uint32_t sb = s2u(dynsmem);
    const int nkt = 2 * qt + 2;
    const size_t trow0 = (size_t)b * TSEQ;
    const int hc = h * DKH;

#pragma unroll
    for (int i = 0; i < 8; ++i) {
        int u = tid + i * 256;
        int arr = u >> 10, r = (u >> 3) & 127, seg = u & 7;
        const __half* src = (arr ? g_ql16 : g_qh16);
        const void* g = src + (trow0 + (size_t)qt * 128 + r) * DMODEL + hc + seg * 8;
        cp16(sb + (arr ? SQLO_OFF : 0) + r * APITCH + seg * 16, g);
    }
    asm volatile("cp.async.commit_group;" ::: "memory");
    load_kv(sb, 0, 0, trow0, hc, tid);
    load_kv(sb, 1, 1, trow0, hc, tid);

    const int a_row = lane & 15;
    const int a_ch2 = ((lane >> 4) << 3) * 2;
    const int b_row = (lane & 7) + ((lane & 16) >> 1);
    const int b_ch2 = (lane & 8) * 2;
    const int rg0 = qt * 128 + 16 * w + (lane >> 2);
    const int cg0 = 2 * (lane & 3);

    asm volatile("cp.async.wait_group 2;" ::: "memory");
    __syncthreads();
    uint32_t qh[4][4], ql[4][4];
#pragma unroll
    for (int t = 0; t < 4; ++t) {
        uint32_t ra = sb + (uint32_t)(16 * w + a_row) * APITCH + t * 32 + a_ch2;
        ldsm_x4(qh[t], ra);
        ldsm_x4(ql[t], ra + SQLO_OFF);
    }

    float m0 = -1e30f, m1 = -1e30f, l0 = 0.f, l1 = 0.f;
    float o[8][4];
#pragma unroll
    for (int j = 0; j < 8; ++j)
#pragma unroll
        for (int q = 0; q < 4; ++q) o[j][q] = 0.f;

    for (int kt = 0; kt < nkt; ++kt) {
        if (kt == nkt - 1)
            asm volatile("cp.async.wait_group 0;" ::: "memory");
        else
            asm volatile("cp.async.wait_group 1;" ::: "memory");
        __syncthreads();
        const uint32_t kvb = sb + KV_BASE + (uint32_t)(kt % 3) * KV_STAGE;

        // S = (Qh+Ql) @ K^T — fp16 2-pass
        float s[8][4];
#pragma unroll
        for (int j = 0; j < 8; ++j)
#pragma unroll
            for (int q = 0; q < 4; ++q) s[j][q] = 0.f;

#pragma unroll
        for (int t = 0; t < 4; ++t) {
            uint32_t th[4][4];
#pragma unroll
            for (int p = 0; p < 4; ++p) {
                uint32_t rb = kvb + (uint32_t)(p * 16 + b_row) * APITCH + t * 32 + b_ch2;
                ldsm_x4(th[p], rb);
            }
#pragma unroll
            for (int p = 0; p < 4; ++p) {
                mma16816h(s[2 * p],     qh[t], &th[p][0]);
                mma16816h(s[2 * p + 1], qh[t], &th[p][2]);
            }
#pragma unroll
            for (int p = 0; p < 4; ++p) {
                mma16816h(s[2 * p],     ql[t], &th[p][0]);
                mma16816h(s[2 * p + 1], ql[t], &th[p][2]);
            }
        }

        if (kt >= nkt - 2) {                   // causal mask (last two tiles)
            const int cb = kt * 64 + cg0;
#pragma unroll
            for (int j = 0; j < 8; ++j) {
                int c0 = cb + 8 * j;
                if (c0     > rg0)     s[j][0] = -1e9f;
                if (c0 + 1 > rg0)     s[j][1] = -1e9f;
                if (c0     > rg0 + 8) s[j][2] = -1e9f;
                if (c0 + 1 > rg0 + 8) s[j][3] = -1e9f;
            }
        }

        // online softmax
        float tm0 = -1e30f, tm1 = -1e30f;
#pragma unroll
        for (int j = 0; j < 8; ++j) {
            tm0 = fmaxf(tm0, fmaxf(s[j][0], s[j][1]));
            tm1 = fmaxf(tm1, fmaxf(s[j][2], s[j][3]));
        }
        tm0 = fmaxf(tm0, __shfl_xor_sync(0xffffffffu, tm0, 1));
        tm0 = fmaxf(tm0, __shfl_xor_sync(0xffffffffu, tm0, 2));
        tm1 = fmaxf(tm1, __shfl_xor_sync(0xffffffffu, tm1, 1));
        tm1 = fmaxf(tm1, __shfl_xor_sync(0xffffffffu, tm1, 2));
        const float mn0 = fmaxf(m0, tm0), mn1 = fmaxf(m1, tm1);
        const float sc0 = __expf(m0 - mn0), sc1 = __expf(m1 - mn1);
        float sum0 = 0.f, sum1 = 0.f;
#pragma unroll
        for (int j = 0; j < 8; ++j) {
            s[j][0] = __expf(s[j][0] - mn0);
            s[j][1] = __expf(s[j][1] - mn0);
            s[j][2] = __expf(s[j][2] - mn1);
            s[j][3] = __expf(s[j][3] - mn1);
            sum0 += s[j][0] + s[j][1];
            sum1 += s[j][2] + s[j][3];
        }
        sum0 += __shfl_xor_sync(0xffffffffu, sum0, 1);
        sum0 += __shfl_xor_sync(0xffffffffu, sum0, 2);
        sum1 += __shfl_xor_sync(0xffffffffu, sum1, 1);
        sum1 += __shfl_xor_sync(0xffffffffu, sum1, 2);
        l0 = l0 * sc0 + sum0;
        l1 = l1 * sc1 + sum1;
        m0 = mn0; m1 = mn1;
#pragma unroll
        for (int j = 0; j < 8; ++j) {
            o[j][0] *= sc0; o[j][1] *= sc0;
            o[j][2] *= sc1; o[j][3] *= sc1;
        }

        // O += (Ph+Pl) @ V — fp16 2-pass
#pragma unroll
        for (int t = 0; t < 4; ++t) {
            uint32_t phi[4], plo[4];
            split2h(s[2 * t][0],     s[2 * t][1],     phi[0], plo[0]);
            split2h(s[2 * t][2],     s[2 * t][3],     phi[1], plo[1]);
            split2h(s[2 * t + 1][0], s[2 * t + 1][1], phi[2], plo[2]);
            split2h(s[2 * t + 1][2], s[2 * t + 1][3], phi[3], plo[3]);
            uint32_t vh[4][4];
#pragma unroll
            for (int np = 0; np < 4; ++np) {
                uint32_t rv = kvb + 9216
                            + (uint32_t)(t * 16 + (lane & 15)) * APITCH
                            + (uint32_t)(np * 16 + ((lane >> 4) << 3)) * 2;
                ldsm_x4_t(vh[np], rv);
            }
#pragma unroll
            for (int np = 0; np < 4; ++np) {
                mma16816h(o[2 * np],     phi, &vh[np][0]);
                mma16816h(o[2 * np + 1], phi, &vh[np][2]);
            }
#pragma unroll
            for (int np = 0; np < 4; ++np) {
                mma16816h(o[2 * np],     plo, &vh[np][0]);
                mma16816h(o[2 * np + 1], plo, &vh[np][2]);
            }
        }

        if (kt + 2 < nkt)
            load_kv(sb, (kt + 2) % 3, kt + 2, trow0, hc, tid);
    }

    // epilogue: ctx = O / l, written as fp16 hi/lo for the fp16 out GEMM
    const float i0 = 1.f / l0, i1 = 1.f / l1;
    const size_t r0t = trow0 + (size_t)qt * 128 + 16 * w + (lane >> 2);
#pragma unroll
    for (int j = 0; j < 8; ++j) {
        const int col = hc + 8 * j + cg0;
        uint32_t hh, ll;
        split2h(o[j][0] * i0, o[j][1] * i0, hh, ll);
        *(uint32_t*)(g_ch + r0t * DMODEL + col) = hh;
        *(uint32_t*)(g_cl + r0t * DMODEL + col) = ll;
        split2h(o[j][2] * i1, o[j][3] * i1, hh, ll);
        *(uint32_t*)(g_ch + (r0t + 8) * DMODEL + col) = hh;
        *(uint32_t*)(g_cl + (r0t + 8) * DMODEL + col) = ll;
    }
}

// ---------------------------------------------------------------------------
extern "C" void kernel_launch(void* const* d_in, const int* in_sizes, int n_in,
                              void* d_out, int out_size) {
    (void)in_sizes; (void)n_in; (void)out_size;
    const float* x  = (const float*)d_in[0];
    // d_in[1]: causal mask — handled analytically.
    const float* Wq = (const float*)d_in[2];
    const float* Wk = (const float*)d_in[3];
    const float* Wv = (const float*)d_in[4];
    const float* Wo = (const float*)d_in[5];
    const float* bo = (const float*)d_in[6];
    float* out = (float*)d_out;

    cudaFuncSetAttribute(qkv_gemm_tc, cudaFuncAttributeMaxDynamicSharedMemorySize, GEMM_SMEM);
    cudaFuncSetAttribute(out_gemm_tc, cudaFuncAttributeMaxDynamicSharedMemorySize, GEMM_SMEM);
    cudaFuncSetAttribute(attn_mma,    cudaFuncAttributeMaxDynamicSharedMemorySize, ATTN_SMEM);

    const int ntot8 = (int)(NX8 + 4 * NW8);
    cvt_all<<<ntot8 / 256, 256>>>(x, Wq, Wk, Wv, Wo);

    qkv_gemm_tc<<<dim3(MROWS / 128, DMODEL / 128, 3), 256, GEMM_SMEM>>>();
    attn_mma<<<dim3(TSEQ / 128, NHEADS, BATCH), 256, ATTN_SMEM>>>();
    out_gemm_tc<<<dim3(MROWS / 128, DMODEL / 128, 1), 256, GEMM_SMEM>>>(bo, out);
}